// round 1
// baseline (speedup 1.0000x reference)
#include <cuda_runtime.h>
#include <cuda_bf16.h>
#include <math.h>

// Problem sizes (fixed per reference)
#define BATCH 4
#define SEQ   4096
#define DMODEL 1024
#define DFF   4096
#define MTOK  (BATCH*SEQ)          // 16384 tokens

// ----------------------------- scratch (static device globals; no allocs) ---
__device__ float g_hin [MTOK*DMODEL];          // rmsnorm1 output      64MB
__device__ float g_lin1[MTOK*DMODEL];          // h_in @ Wg            64MB
__device__ float g_lin2[MTOK*DMODEL];          // h_in @ Wc            64MB
__device__ float g_at  [BATCH*DMODEL*SEQ];     // gates  [b,d,t]       64MB
__device__ float g_bt  [BATCH*DMODEL*SEQ];     // (1-g)*c -> h [b,d,t] 64MB
__device__ float g_fin [MTOK*DMODEL];          // rmsnorm2 output      64MB
__device__ float g_u1  [MTOK*DFF];             // f_in @ W1 -> silu*u2 256MB
__device__ float g_u2  [MTOK*DFF];             // f_in @ W3            256MB

// ----------------------------- RMSNorm: one block per token row of 1024 ----
__global__ __launch_bounds__(256) void rmsnorm_kernel(
    const float* __restrict__ x, const float* __restrict__ w, float* __restrict__ y)
{
    int row = blockIdx.x;
    int tid = threadIdx.x;
    const float4* xr = (const float4*)(x + (long)row * DMODEL);
    float4 v = xr[tid];
    float ss = v.x*v.x + v.y*v.y + v.z*v.z + v.w*v.w;
    #pragma unroll
    for (int o = 16; o; o >>= 1) ss += __shfl_xor_sync(0xffffffffu, ss, o);
    __shared__ float sred[8];
    if ((tid & 31) == 0) sred[tid >> 5] = ss;
    __syncthreads();
    if (tid < 8) {
        float t = sred[tid];
        #pragma unroll
        for (int o = 4; o; o >>= 1) t += __shfl_xor_sync(0xffu, t, o);
        if (tid == 0) sred[0] = t;
    }
    __syncthreads();
    float scale = rsqrtf(sred[0] * (1.0f / DMODEL) + 1e-6f);
    float4 wv = ((const float4*)w)[tid];
    float4 o4 = make_float4(v.x*scale*wv.x, v.y*scale*wv.y,
                            v.z*scale*wv.z, v.w*scale*wv.w);
    ((float4*)(y + (long)row * DMODEL))[tid] = o4;
}

// ----------------------------- SGEMM 128x128x16, 256 thr, 8x8 microtile ----
// C[M,N] = A[M,K] @ B[K,N]  (+ Cin if MODE==1).  M%128==0, N%128==0, K%16==0.
template<int MODE>
__global__ __launch_bounds__(256) void gemm_kernel(
    const float* __restrict__ A, const float* __restrict__ B,
    float* __restrict__ C, const float* __restrict__ Cin,
    int M, int N, int K)
{
    __shared__ float As[16][128];
    __shared__ float Bs[16][128];
    int tid = threadIdx.x;
    int m0 = blockIdx.y * 128;
    int n0 = blockIdx.x * 128;

    int aRow = tid >> 2;          // 0..63
    int aCol = (tid & 3) << 2;    // 0,4,8,12
    int bRow = tid >> 5;          // 0..7
    int bCol = (tid & 31) << 2;   // 0..124

    int tr = (tid >> 4) << 3;     // 0..120
    int tc = (tid & 15) << 3;     // 0..120

    float acc[8][8] = {};
    float regM[8], regN[8];

    const float* Aptr = A + (long)m0 * K;
    const float* Bptr = B + n0;

    for (int k0 = 0; k0 < K; k0 += 16) {
        #pragma unroll
        for (int r = 0; r < 2; r++) {
            int row = aRow + r * 64;
            float4 v = *(const float4*)(Aptr + (long)row * K + k0 + aCol);
            As[aCol + 0][row] = v.x;
            As[aCol + 1][row] = v.y;
            As[aCol + 2][row] = v.z;
            As[aCol + 3][row] = v.w;
        }
        #pragma unroll
        for (int r = 0; r < 2; r++) {
            int row = bRow + r * 8;
            float4 v = *(const float4*)(Bptr + (long)(k0 + row) * N + bCol);
            *(float4*)(&Bs[row][bCol]) = v;
        }
        __syncthreads();
        #pragma unroll
        for (int k = 0; k < 16; k++) {
            *(float4*)&regM[0] = *(const float4*)&As[k][tr];
            *(float4*)&regM[4] = *(const float4*)&As[k][tr + 4];
            *(float4*)&regN[0] = *(const float4*)&Bs[k][tc];
            *(float4*)&regN[4] = *(const float4*)&Bs[k][tc + 4];
            #pragma unroll
            for (int i = 0; i < 8; i++)
                #pragma unroll
                for (int j = 0; j < 8; j++)
                    acc[i][j] += regM[i] * regN[j];
        }
        __syncthreads();
    }

    #pragma unroll
    for (int i = 0; i < 8; i++) {
        long crow = (long)(m0 + tr + i) * N + n0 + tc;
        #pragma unroll
        for (int j4 = 0; j4 < 8; j4 += 4) {
            float4 v = make_float4(acc[i][j4], acc[i][j4+1], acc[i][j4+2], acc[i][j4+3]);
            if (MODE == 1) {
                float4 cv = *(const float4*)(Cin + crow + j4);
                v.x += cv.x; v.y += cv.y; v.z += cv.z; v.w += cv.w;
            }
            *(float4*)(C + crow + j4) = v;
        }
    }
}

// --------------- gates/cands activation + transpose to [b,d,t] -------------
__global__ void gate_transpose(
    const float* __restrict__ lin1, const float* __restrict__ lin2,
    const float* __restrict__ bg, const float* __restrict__ bc,
    float* __restrict__ at, float* __restrict__ bt)
{
    __shared__ float sa[32][33];
    __shared__ float sb[32][33];
    int t0 = blockIdx.x * 32, d0 = blockIdx.y * 32, bb = blockIdx.z;
    int tx = threadIdx.x, ty = threadIdx.y;
    int d = d0 + tx;
    float bgv = bg[d], bcv = bc[d];
    #pragma unroll
    for (int i = 0; i < 4; i++) {
        int t = t0 + ty + i * 8;
        long idx = ((long)(bb * SEQ + t)) * DMODEL + d;
        float g = 1.f / (1.f + expf(-(lin1[idx] + bgv)));
        float c = tanhf(lin2[idx] + bcv);
        sa[ty + i * 8][tx] = g;
        sb[ty + i * 8][tx] = (1.f - g) * c;
    }
    __syncthreads();
    #pragma unroll
    for (int i = 0; i < 4; i++) {
        int dd = d0 + ty + i * 8;
        int t  = t0 + tx;
        long o = ((long)(bb * DMODEL + dd)) * SEQ + t;
        at[o] = sa[tx][ty + i * 8];
        bt[o] = sb[tx][ty + i * 8];
    }
}

// --------------- per-(b,d) linear-recurrence scan over t (L=4096) ----------
// element e=(a,b); combine(prev,cur) = (a_p*a_c, a_c*b_p + b_c); h = B-part.
__global__ __launch_bounds__(256) void scan_kernel(
    const float* __restrict__ at, float* __restrict__ bt)
{
    long base = (long)blockIdx.x * SEQ;
    int tid = threadIdx.x;
    float la[16], lb[16];
    const float4* ap = (const float4*)(at + base) + tid * 4;
    float4*       bp = (float4*)(bt + base) + tid * 4;
    #pragma unroll
    for (int q = 0; q < 4; q++) { ((float4*)la)[q] = ap[q]; ((float4*)lb)[q] = bp[q]; }

    float A = 1.f, Bc = 0.f;
    #pragma unroll
    for (int j = 0; j < 16; j++) { Bc = la[j] * Bc + lb[j]; A *= la[j]; }

    __shared__ float sA[256], sB[256];
    sA[tid] = A; sB[tid] = Bc;
    __syncthreads();
    #pragma unroll
    for (int off = 1; off < 256; off <<= 1) {
        float pA = 1.f, pB = 0.f;
        if (tid >= off) { pA = sA[tid - off]; pB = sB[tid - off]; }
        float cA = sA[tid], cB = sB[tid];
        __syncthreads();
        sA[tid] = pA * cA;
        sB[tid] = cA * pB + cB;
        __syncthreads();
    }
    float carry = (tid > 0) ? sB[tid - 1] : 0.f;
    #pragma unroll
    for (int j = 0; j < 16; j++) { carry = la[j] * carry + lb[j]; lb[j] = carry; }
    #pragma unroll
    for (int q = 0; q < 4; q++) bp[q] = ((float4*)lb)[q];
}

// --------------- residual: y[b,t,d] = x[b,t,d] + h[b,d,t] ------------------
__global__ void residual_add_t(
    const float* __restrict__ x, const float* __restrict__ ht, float* __restrict__ y)
{
    __shared__ float s[32][33];
    int t0 = blockIdx.x * 32, d0 = blockIdx.y * 32, bb = blockIdx.z;
    int tx = threadIdx.x, ty = threadIdx.y;
    #pragma unroll
    for (int i = 0; i < 4; i++) {
        int dd = d0 + ty + i * 8;
        int t  = t0 + tx;
        s[ty + i * 8][tx] = ht[((long)(bb * DMODEL + dd)) * SEQ + t];
    }
    __syncthreads();
    #pragma unroll
    for (int i = 0; i < 4; i++) {
        int t = t0 + ty + i * 8;
        int d = d0 + tx;
        long idx = ((long)(bb * SEQ + t)) * DMODEL + d;
        y[idx] = x[idx] + s[tx][ty + i * 8];
    }
}

// --------------- u1 = silu(u1) * u2 ----------------------------------------
__global__ __launch_bounds__(256) void silu_mul(
    float* __restrict__ u1, const float* __restrict__ u2, long n4)
{
    long i = (long)blockIdx.x * blockDim.x + threadIdx.x;
    if (i < n4) {
        float4 a = ((const float4*)u1)[i];
        float4 b = ((const float4*)u2)[i];
        a.x = a.x / (1.f + expf(-a.x)) * b.x;
        a.y = a.y / (1.f + expf(-a.y)) * b.y;
        a.z = a.z / (1.f + expf(-a.z)) * b.z;
        a.w = a.w / (1.f + expf(-a.w)) * b.w;
        ((float4*)u1)[i] = a;
    }
}

// ----------------------------------------------------------------------------
extern "C" void kernel_launch(void* const* d_in, const int* in_sizes, int n_in,
                              void* d_out, int out_size)
{
    const float* x   = (const float*)d_in[0];
    const float* Wg  = (const float*)d_in[1];
    const float* bg  = (const float*)d_in[2];
    const float* Wc  = (const float*)d_in[3];
    const float* bc  = (const float*)d_in[4];
    const float* n1w = (const float*)d_in[5];
    const float* n2w = (const float*)d_in[6];
    const float* W1  = (const float*)d_in[7];
    const float* W3  = (const float*)d_in[8];
    const float* W2  = (const float*)d_in[9];
    float* out = (float*)d_out;

    float *hin, *lin1, *lin2, *at, *bt, *fin, *u1, *u2;
    cudaGetSymbolAddress((void**)&hin,  g_hin);
    cudaGetSymbolAddress((void**)&lin1, g_lin1);
    cudaGetSymbolAddress((void**)&lin2, g_lin2);
    cudaGetSymbolAddress((void**)&at,   g_at);
    cudaGetSymbolAddress((void**)&bt,   g_bt);
    cudaGetSymbolAddress((void**)&fin,  g_fin);
    cudaGetSymbolAddress((void**)&u1,   g_u1);
    cudaGetSymbolAddress((void**)&u2,   g_u2);

    // 1) h_in = rmsnorm(x, n1_w)
    rmsnorm_kernel<<<MTOK, 256>>>(x, n1w, hin);

    // 2) gate / candidate linears
    dim3 gD(DMODEL / 128, MTOK / 128);   // (8,128)
    gemm_kernel<0><<<gD, 256>>>(hin, Wg, lin1, nullptr, MTOK, DMODEL, DMODEL);
    gemm_kernel<0><<<gD, 256>>>(hin, Wc, lin2, nullptr, MTOK, DMODEL, DMODEL);

    // 3) activations + transpose to [b,d,t]
    dim3 gT(SEQ / 32, DMODEL / 32, BATCH);
    gate_transpose<<<gT, dim3(32, 8)>>>(lin1, lin2, bg, bc, at, bt);

    // 4) associative scan along t (in place into bt)
    scan_kernel<<<BATCH * DMODEL, 256>>>(at, bt);

    // 5) x2 = x + h  (out holds x2)
    residual_add_t<<<gT, dim3(32, 8)>>>(x, bt, out);

    // 6) f_in = rmsnorm(x2, n2_w)
    rmsnorm_kernel<<<MTOK, 256>>>(out, n2w, fin);

    // 7) SwiGLU up projections
    dim3 gF(DFF / 128, MTOK / 128);      // (32,128)
    gemm_kernel<0><<<gF, 256>>>(fin, W1, u1, nullptr, MTOK, DFF, DMODEL);
    gemm_kernel<0><<<gF, 256>>>(fin, W3, u2, nullptr, MTOK, DFF, DMODEL);

    // 8) u1 = silu(u1) * u2
    long n4 = (long)MTOK * DFF / 4;
    silu_mul<<<(unsigned)((n4 + 255) / 256), 256>>>(u1, u2, n4);

    // 9) out = x2 + u1 @ W2   (residual fused in epilogue; Cin==C==out)
    gemm_kernel<1><<<gD, 256>>>(u1, W2, out, out, MTOK, DMODEL, DFF);
}

// round 3
// speedup vs baseline: 3.3363x; 3.3363x over previous
#include <cuda_runtime.h>
#include <cuda_bf16.h>
#include <math.h>
#include <stdint.h>

#define BATCH 4
#define SEQ   4096
#define DMODEL 1024
#define DFF   4096
#define MTOK  (BATCH*SEQ)

// GEMM tiling
#define BM 128
#define BN 128
#define BKK 32
#define STAGES 3
#define ASTRIDE 36                                  // 32 + 4 pad floats
#define STAGE_FLOATS (BM*ASTRIDE + BN*ASTRIDE)      // 9216
#define GSMEM (STAGES*STAGE_FLOATS*4)               // 110592 bytes

// Epilogue modes
#define M_SILU 0   // O = silu(acc)                     [tok, ldo]
#define M_MUL  1   // O = tf32(AUX * acc)               [tok, ldo]
#define M_RES  2   // O += acc                          [tok, ldo]
#define M_GATG 3   // O[b,n,t] = sigmoid(acc + bias[n])
#define M_GATC 4   // O[b,n,t] = (1 - AUX[b,n,t]) * tanh(acc + bias[n])

// ------------------------- scratch -----------------------------------------
__device__ float g_hin[MTOK*DMODEL];
__device__ float g_fin[MTOK*DMODEL];
__device__ float g_at [BATCH*DMODEL*SEQ];
__device__ float g_bt [BATCH*DMODEL*SEQ];
__device__ float g_u1 [(size_t)MTOK*DFF];
__device__ float g_u  [(size_t)MTOK*DFF];
__device__ float g_WgT[DMODEL*DMODEL];
__device__ float g_WcT[DMODEL*DMODEL];
__device__ float g_W1T[(size_t)DFF*DMODEL];
__device__ float g_W3T[(size_t)DFF*DMODEL];
__device__ float g_W2T[(size_t)DMODEL*DFF];

// ------------------------- helpers -----------------------------------------
__device__ __forceinline__ uint32_t smem_u32(const void* p) {
    uint32_t a;
    asm("{ .reg .u64 t; cvta.to.shared.u64 t, %1; cvt.u32.u64 %0, t; }"
        : "=r"(a) : "l"(p));
    return a;
}
__device__ __forceinline__ float tf32r(float x) {
    float r; asm("cvt.rn.tf32.f32 %0, %1;" : "=f"(r) : "f"(x)); return r;
}
#define CPA16(dst, src) \
    asm volatile("cp.async.cg.shared.global [%0], [%1], 16;" :: "r"(dst), "l"(src))
#define CPA_COMMIT() asm volatile("cp.async.commit_group;" ::: "memory")
#define CPA_WAIT1()  asm volatile("cp.async.wait_group 1;"  ::: "memory")

__device__ __forceinline__ void mma8(float c[4], const float a[4], const float b[2]) {
    asm volatile(
        "mma.sync.aligned.m16n8k8.row.col.f32.tf32.tf32.f32 "
        "{%0,%1,%2,%3},{%4,%5,%6,%7},{%8,%9},{%0,%1,%2,%3};"
        : "+f"(c[0]), "+f"(c[1]), "+f"(c[2]), "+f"(c[3])
        : "r"(__float_as_uint(a[0])), "r"(__float_as_uint(a[1])),
          "r"(__float_as_uint(a[2])), "r"(__float_as_uint(a[3])),
          "r"(__float_as_uint(b[0])), "r"(__float_as_uint(b[1])));
}

// ------------------------- tensor-core GEMM (mma.sync tf32) ----------------
// C[M,N] = A[M,K] @ BT[N,K]^T ; A,BT tf32-pre-rounded fp32.
template<int MODE>
__global__ __launch_bounds__(256, 1) void gemm_mma(
    const float* __restrict__ A, const float* __restrict__ BT,
    float* __restrict__ O, const float* __restrict__ bias,
    const float* __restrict__ AUX, int K, int ldo)
{
    extern __shared__ float sm[];
    const uint32_t sbase = smem_u32(sm);
    const int tid = threadIdx.x, lane = tid & 31, wid = tid >> 5;
    const int wm = wid & 1, wn = wid >> 1;         // warp tile: 64(m) x 32(n)
    const int m0 = blockIdx.y * BM, n0 = blockIdx.x * BN;
    const int NK = K / BKK;

    float acc[4][4][4] = {};

    // ---- prologue: fill STAGES-1 stages ----
    #pragma unroll
    for (int ps = 0; ps < STAGES - 1; ps++) {
        const float* Ag = A  + (long)m0 * K + ps * BKK;
        const float* Bg = BT + (long)n0 * K + ps * BKK;
        uint32_t abase = sbase + ps * STAGE_FLOATS * 4;
        uint32_t bbase = abase + BM * ASTRIDE * 4;
        #pragma unroll
        for (int i = 0; i < 4; i++) {
            int id = tid + i * 256;
            int row = id >> 3, kc = (id & 7) * 4;
            CPA16(abase + (row * ASTRIDE + kc) * 4, Ag + (long)row * K + kc);
            CPA16(bbase + (row * ASTRIDE + kc) * 4, Bg + (long)row * K + kc);
        }
        CPA_COMMIT();
    }

    for (int kt = 0; kt < NK; kt++) {
        CPA_WAIT1();
        __syncthreads();
        const float* As = sm + (kt % STAGES) * STAGE_FLOATS;
        const float* Bs = As + BM * ASTRIDE;
        #pragma unroll
        for (int ks = 0; ks < 4; ks++) {
            const int k0 = ks * 8;
            float af[4][4], bf[4][2];
            #pragma unroll
            for (int i = 0; i < 4; i++) {
                const float* ap = As + (wm*64 + i*16 + (lane>>2)) * ASTRIDE + k0 + (lane&3);
                af[i][0] = ap[0];
                af[i][1] = ap[8*ASTRIDE];
                af[i][2] = ap[4];
                af[i][3] = ap[8*ASTRIDE + 4];
            }
            #pragma unroll
            for (int j = 0; j < 4; j++) {
                const float* bp = Bs + (wn*32 + j*8 + (lane>>2)) * ASTRIDE + k0 + (lane&3);
                bf[j][0] = bp[0];
                bf[j][1] = bp[4];
            }
            #pragma unroll
            for (int i = 0; i < 4; i++)
                #pragma unroll
                for (int j = 0; j < 4; j++)
                    mma8(acc[i][j], af[i], bf[j]);
        }
        int nxt = kt + STAGES - 1;
        if (nxt < NK) {
            const float* Ag = A  + (long)m0 * K + nxt * BKK;
            const float* Bg = BT + (long)n0 * K + nxt * BKK;
            uint32_t abase = sbase + (nxt % STAGES) * STAGE_FLOATS * 4;
            uint32_t bbase = abase + BM * ASTRIDE * 4;
            #pragma unroll
            for (int i = 0; i < 4; i++) {
                int id = tid + i * 256;
                int row = id >> 3, kc = (id & 7) * 4;
                CPA16(abase + (row * ASTRIDE + kc) * 4, Ag + (long)row * K + kc);
                CPA16(bbase + (row * ASTRIDE + kc) * 4, Bg + (long)row * K + kc);
            }
        }
        CPA_COMMIT();
    }
    __syncthreads();    // smem reuse for epilogue patches

    // ---------------- epilogue ----------------
    if (MODE == M_SILU || MODE == M_MUL || MODE == M_RES) {
        #pragma unroll
        for (int i = 0; i < 4; i++) {
            #pragma unroll
            for (int j = 0; j < 4; j++) {
                int r0 = m0 + wm*64 + i*16 + (lane>>2);
                int c0 = n0 + wn*32 + j*8 + 2*(lane&3);
                long o0 = (long)r0 * ldo + c0;
                long o1 = o0 + (long)8 * ldo;
                float v0 = acc[i][j][0], v1 = acc[i][j][1];
                float v2 = acc[i][j][2], v3 = acc[i][j][3];
                if (MODE == M_SILU) {
                    v0 = v0 / (1.f + __expf(-v0));
                    v1 = v1 / (1.f + __expf(-v1));
                    v2 = v2 / (1.f + __expf(-v2));
                    v3 = v3 / (1.f + __expf(-v3));
                } else if (MODE == M_MUL) {
                    float2 u0 = *(const float2*)(AUX + o0);
                    float2 u1 = *(const float2*)(AUX + o1);
                    v0 = tf32r(u0.x * v0); v1 = tf32r(u0.y * v1);
                    v2 = tf32r(u1.x * v2); v3 = tf32r(u1.y * v3);
                } else {
                    float2 p0 = *(const float2*)(O + o0);
                    float2 p1 = *(const float2*)(O + o1);
                    v0 += p0.x; v1 += p0.y; v2 += p1.x; v3 += p1.y;
                }
                *(float2*)(O + o0) = make_float2(v0, v1);
                *(float2*)(O + o1) = make_float2(v2, v3);
            }
        }
    } else {
        // transposed gate epilogue: stage warp tile, write [b, n, t] rows
        float* patch = sm + wid * (32 * 65);
        #pragma unroll
        for (int i = 0; i < 4; i++) {
            #pragma unroll
            for (int j = 0; j < 4; j++) {
                int r0 = i*16 + (lane>>2);
                int c0 = j*8 + 2*(lane&3);
                patch[c0*65 + r0]         = acc[i][j][0];
                patch[(c0+1)*65 + r0]     = acc[i][j][1];
                patch[c0*65 + r0 + 8]     = acc[i][j][2];
                patch[(c0+1)*65 + r0 + 8] = acc[i][j][3];
            }
        }
        __syncwarp();
        int tokb = m0 + wm * 64;
        int b = tokb >> 12, tb = tokb & 4095;
        #pragma unroll 4
        for (int r = 0; r < 32; r++) {
            int n = n0 + wn*32 + r;
            float bs = bias[n];
            float v0 = patch[r*65 + lane*2];
            float v1 = patch[r*65 + lane*2 + 1];
            long off = ((long)(b * DMODEL + n)) * SEQ + tb + lane*2;
            if (MODE == M_GATG) {
                float g0 = 1.f / (1.f + __expf(-(v0 + bs)));
                float g1 = 1.f / (1.f + __expf(-(v1 + bs)));
                *(float2*)(O + off) = make_float2(g0, g1);
            } else {
                float2 g = *(const float2*)(AUX + off);
                float c0 = tanhf(v0 + bs);
                float c1 = tanhf(v1 + bs);
                *(float2*)(O + off) = make_float2((1.f - g.x) * c0, (1.f - g.y) * c1);
            }
        }
    }
}

// ------------------------- RMSNorm (tf32-rounded output) -------------------
__global__ __launch_bounds__(256) void rmsnorm_kernel(
    const float* __restrict__ x, const float* __restrict__ w, float* __restrict__ y)
{
    int row = blockIdx.x, tid = threadIdx.x;
    float4 v = ((const float4*)(x + (long)row * DMODEL))[tid];
    float ss = v.x*v.x + v.y*v.y + v.z*v.z + v.w*v.w;
    #pragma unroll
    for (int o = 16; o; o >>= 1) ss += __shfl_xor_sync(0xffffffffu, ss, o);
    __shared__ float sred[8];
    if ((tid & 31) == 0) sred[tid >> 5] = ss;
    __syncthreads();
    if (tid < 8) {
        float t = sred[tid];
        #pragma unroll
        for (int o = 4; o; o >>= 1) t += __shfl_xor_sync(0xffu, t, o);
        if (tid == 0) sred[0] = t;
    }
    __syncthreads();
    float scale = rsqrtf(sred[0] * (1.0f / DMODEL) + 1e-6f);
    float4 wv = ((const float4*)w)[tid];
    float4 o4 = make_float4(tf32r(v.x*scale*wv.x), tf32r(v.y*scale*wv.y),
                            tf32r(v.z*scale*wv.z), tf32r(v.w*scale*wv.w));
    ((float4*)(y + (long)row * DMODEL))[tid] = o4;
}

// ------------------------- weight transpose + tf32 round -------------------
__global__ void transpose_tf32(const float* __restrict__ W, float* __restrict__ WT,
                               int K, int N)
{
    __shared__ float s[32][33];
    int n0 = blockIdx.x * 32, k0 = blockIdx.y * 32;
    int tx = threadIdx.x, ty = threadIdx.y;
    #pragma unroll
    for (int i = 0; i < 4; i++)
        s[ty + i * 8][tx] = W[(long)(k0 + ty + i * 8) * N + n0 + tx];
    __syncthreads();
    #pragma unroll
    for (int i = 0; i < 4; i++)
        WT[(long)(n0 + ty + i * 8) * K + k0 + tx] = tf32r(s[tx][ty + i * 8]);
}

// ------------------------- scan over t (per (b,d) row) ---------------------
__global__ __launch_bounds__(256) void scan_kernel(
    const float* __restrict__ at, float* __restrict__ bt)
{
    long base = (long)blockIdx.x * SEQ;
    int tid = threadIdx.x;
    float la[16], lb[16];
    const float4* ap = (const float4*)(at + base) + tid * 4;
    float4*       bp = (float4*)(bt + base) + tid * 4;
    #pragma unroll
    for (int q = 0; q < 4; q++) { ((float4*)la)[q] = ap[q]; ((float4*)lb)[q] = bp[q]; }
    float A = 1.f, Bc = 0.f;
    #pragma unroll
    for (int j = 0; j < 16; j++) { Bc = la[j] * Bc + lb[j]; A *= la[j]; }
    __shared__ float sA[256], sB[256];
    sA[tid] = A; sB[tid] = Bc;
    __syncthreads();
    #pragma unroll
    for (int off = 1; off < 256; off <<= 1) {
        float pA = 1.f, pB = 0.f;
        if (tid >= off) { pA = sA[tid - off]; pB = sB[tid - off]; }
        float cA = sA[tid], cB = sB[tid];
        __syncthreads();
        sA[tid] = pA * cA;
        sB[tid] = cA * pB + cB;
        __syncthreads();
    }
    float carry = (tid > 0) ? sB[tid - 1] : 0.f;
    #pragma unroll
    for (int j = 0; j < 16; j++) { carry = la[j] * carry + lb[j]; lb[j] = carry; }
    #pragma unroll
    for (int q = 0; q < 4; q++) bp[q] = ((float4*)lb)[q];
}

// ------------------------- y[b,t,d] = x[b,t,d] + h[b,d,t] ------------------
__global__ void residual_add_t(
    const float* __restrict__ x, const float* __restrict__ ht, float* __restrict__ y)
{
    __shared__ float s[32][33];
    int t0 = blockIdx.x * 32, d0 = blockIdx.y * 32, bb = blockIdx.z;
    int tx = threadIdx.x, ty = threadIdx.y;
    #pragma unroll
    for (int i = 0; i < 4; i++)
        s[ty + i * 8][tx] = ht[((long)(bb * DMODEL + d0 + ty + i * 8)) * SEQ + t0 + tx];
    __syncthreads();
    #pragma unroll
    for (int i = 0; i < 4; i++) {
        long idx = ((long)(bb * SEQ + t0 + ty + i * 8)) * DMODEL + d0 + tx;
        y[idx] = x[idx] + s[tx][ty + i * 8];
    }
}

// ----------------------------------------------------------------------------
extern "C" void kernel_launch(void* const* d_in, const int* in_sizes, int n_in,
                              void* d_out, int out_size)
{
    const float* x   = (const float*)d_in[0];
    const float* Wg  = (const float*)d_in[1];
    const float* bg  = (const float*)d_in[2];
    const float* Wc  = (const float*)d_in[3];
    const float* bc  = (const float*)d_in[4];
    const float* n1w = (const float*)d_in[5];
    const float* n2w = (const float*)d_in[6];
    const float* W1  = (const float*)d_in[7];
    const float* W3  = (const float*)d_in[8];
    const float* W2  = (const float*)d_in[9];
    float* out = (float*)d_out;

    float *hin, *fin, *at, *bt, *u1, *u, *WgT, *WcT, *W1T, *W3T, *W2T;
    cudaGetSymbolAddress((void**)&hin, g_hin);
    cudaGetSymbolAddress((void**)&fin, g_fin);
    cudaGetSymbolAddress((void**)&at,  g_at);
    cudaGetSymbolAddress((void**)&bt,  g_bt);
    cudaGetSymbolAddress((void**)&u1,  g_u1);
    cudaGetSymbolAddress((void**)&u,   g_u);
    cudaGetSymbolAddress((void**)&WgT, g_WgT);
    cudaGetSymbolAddress((void**)&WcT, g_WcT);
    cudaGetSymbolAddress((void**)&W1T, g_W1T);
    cudaGetSymbolAddress((void**)&W3T, g_W3T);
    cudaGetSymbolAddress((void**)&W2T, g_W2T);

    cudaFuncSetAttribute(gemm_mma<M_SILU>, cudaFuncAttributeMaxDynamicSharedMemorySize, GSMEM);
    cudaFuncSetAttribute(gemm_mma<M_MUL>,  cudaFuncAttributeMaxDynamicSharedMemorySize, GSMEM);
    cudaFuncSetAttribute(gemm_mma<M_RES>,  cudaFuncAttributeMaxDynamicSharedMemorySize, GSMEM);
    cudaFuncSetAttribute(gemm_mma<M_GATG>, cudaFuncAttributeMaxDynamicSharedMemorySize, GSMEM);
    cudaFuncSetAttribute(gemm_mma<M_GATC>, cudaFuncAttributeMaxDynamicSharedMemorySize, GSMEM);

    // 0) weight transposes to [N,K] + tf32 rounding
    transpose_tf32<<<dim3(DMODEL/32, DMODEL/32), dim3(32, 8)>>>(Wg, WgT, DMODEL, DMODEL);
    transpose_tf32<<<dim3(DMODEL/32, DMODEL/32), dim3(32, 8)>>>(Wc, WcT, DMODEL, DMODEL);
    transpose_tf32<<<dim3(DFF/32,    DMODEL/32), dim3(32, 8)>>>(W1, W1T, DMODEL, DFF);
    transpose_tf32<<<dim3(DFF/32,    DMODEL/32), dim3(32, 8)>>>(W3, W3T, DMODEL, DFF);
    transpose_tf32<<<dim3(DMODEL/32, DFF/32),    dim3(32, 8)>>>(W2, W2T, DFF, DMODEL);

    // 1) h_in = rmsnorm(x, n1_w)
    rmsnorm_kernel<<<MTOK, 256>>>(x, n1w, hin);

    // 2) gates: at = sigmoid(hin@WgT + bg) in [b,d,t]
    gemm_mma<M_GATG><<<dim3(DMODEL/BN, MTOK/BM), 256, GSMEM>>>(
        hin, WgT, at, bg, nullptr, DMODEL, 0);
    // 3) cands: bt = (1 - at) * tanh(hin@WcT + bc) in [b,d,t]
    gemm_mma<M_GATC><<<dim3(DMODEL/BN, MTOK/BM), 256, GSMEM>>>(
        hin, WcT, bt, bc, at, DMODEL, 0);

    // 4) linear-recurrence scan along t (in place in bt)
    scan_kernel<<<BATCH * DMODEL, 256>>>(at, bt);

    // 5) x2 = x + h -> out
    residual_add_t<<<dim3(SEQ/32, DMODEL/32, BATCH), dim3(32, 8)>>>(x, bt, out);

    // 6) f_in = rmsnorm(x2, n2_w)
    rmsnorm_kernel<<<MTOK, 256>>>(out, n2w, fin);

    // 7) u1 = silu(fin@W1T)
    gemm_mma<M_SILU><<<dim3(DFF/BN, MTOK/BM), 256, GSMEM>>>(
        fin, W1T, u1, nullptr, nullptr, DMODEL, DFF);
    // 8) u = tf32(u1 * (fin@W3T))
    gemm_mma<M_MUL><<<dim3(DFF/BN, MTOK/BM), 256, GSMEM>>>(
        fin, W3T, u, nullptr, u1, DMODEL, DFF);

    // 9) out = x2 + u@W2T (residual fused)
    gemm_mma<M_RES><<<dim3(DMODEL/BN, MTOK/BM), 256, GSMEM>>>(
        u, W2T, out, nullptr, nullptr, DFF, DMODEL);
}

// round 4
// speedup vs baseline: 3.9169x; 1.1740x over previous
#include <cuda_runtime.h>
#include <cuda_bf16.h>
#include <math.h>
#include <stdint.h>

#define BATCH 4
#define SEQ   4096
#define DMODEL 1024
#define DFF   4096
#define MTOK  (BATCH*SEQ)

// GEMM tiling
#define BM 128
#define BN 128
#define BKK 32
#define ASTRIDE 36

// single-B kernel (W2)
#define SSTAGES 3
#define SSTAGE_FLOATS ((BM + BN) * ASTRIDE)          // 9216
#define SSMEM (SSTAGES * SSTAGE_FLOATS * 4)          // 110592

// dual-B kernel
#define DSTAGES 4
#define DSTAGE_FLOATS ((BM + 2*BN) * ASTRIDE)        // 13824
#define DSMEM (DSTAGES * DSTAGE_FLOATS * 4)          // 221184

#define M_GATES 0
#define M_FF    1

// ------------------------- scratch -----------------------------------------
__device__ float g_hin[MTOK*DMODEL];
__device__ float g_fin[MTOK*DMODEL];
__device__ float g_at [BATCH*DMODEL*SEQ];
__device__ float g_bt [BATCH*DMODEL*SEQ];
__device__ float g_u  [(size_t)MTOK*DFF];
__device__ float g_WgT[DMODEL*DMODEL];
__device__ float g_WcT[DMODEL*DMODEL];
__device__ float g_W1T[(size_t)DFF*DMODEL];
__device__ float g_W3T[(size_t)DFF*DMODEL];
__device__ float g_W2T[(size_t)DMODEL*DFF];

// ------------------------- helpers -----------------------------------------
__device__ __forceinline__ uint32_t smem_u32(const void* p) {
    uint32_t a;
    asm("{ .reg .u64 t; cvta.to.shared.u64 t, %1; cvt.u32.u64 %0, t; }"
        : "=r"(a) : "l"(p));
    return a;
}
__device__ __forceinline__ float tf32r(float x) {
    float r; asm("cvt.rn.tf32.f32 %0, %1;" : "=f"(r) : "f"(x)); return r;
}
#define CPA16(dst, src) \
    asm volatile("cp.async.cg.shared.global [%0], [%1], 16;" :: "r"(dst), "l"(src))
#define CPA_COMMIT() asm volatile("cp.async.commit_group;" ::: "memory")
#define CPA_WAITG(n) asm volatile("cp.async.wait_group %0;" :: "n"(n) : "memory")

__device__ __forceinline__ void mma8(float c[4], const float a[4], const float b[2]) {
    asm volatile(
        "mma.sync.aligned.m16n8k8.row.col.f32.tf32.tf32.f32 "
        "{%0,%1,%2,%3},{%4,%5,%6,%7},{%8,%9},{%0,%1,%2,%3};"
        : "+f"(c[0]), "+f"(c[1]), "+f"(c[2]), "+f"(c[3])
        : "r"(__float_as_uint(a[0])), "r"(__float_as_uint(a[1])),
          "r"(__float_as_uint(a[2])), "r"(__float_as_uint(a[3])),
          "r"(__float_as_uint(b[0])), "r"(__float_as_uint(b[1])));
}

// ------------------------- dual-B tensor-core GEMM -------------------------
// Computes acc1 = A@B1T^T, acc2 = A@B2T^T sharing the A pipeline.
// MODE M_GATES: at[b,n,t] = sigmoid(acc1+bg[n]); bt[b,n,t] = (1-g)*tanh(acc2+bc[n])
// MODE M_FF:    O1[tok,DFF] = tf32(silu(acc1) * acc2)
template<int MODE>
__global__ __launch_bounds__(256, 1) void gemm_dual(
    const float* __restrict__ A, const float* __restrict__ B1T,
    const float* __restrict__ B2T,
    float* __restrict__ O1, float* __restrict__ O2,
    const float* __restrict__ bias1, const float* __restrict__ bias2,
    int K)
{
    extern __shared__ float sm[];
    const uint32_t sbase = smem_u32(sm);
    const int tid = threadIdx.x, lane = tid & 31, wid = tid >> 5;
    const int wm = wid & 1, wn = wid >> 1;     // warp tile 64(m) x 32(n) per output
    const int m0 = blockIdx.y * BM, n0 = blockIdx.x * BN;
    const int NK = K / BKK;

    float acc1[4][4][4] = {};
    float acc2[4][4][4] = {};

    // ---- load helper (12 cp16 per thread per stage) ----
    #define DLOAD(stage, ktile)                                                 \
    {                                                                           \
        uint32_t base = sbase + (stage) * DSTAGE_FLOATS * 4;                    \
        long koff = (long)(ktile) * BKK;                                        \
        _Pragma("unroll")                                                       \
        for (int i = 0; i < 12; i++) {                                          \
            int id = tid + i * 256;                                             \
            int row = id >> 3, kc = (id & 7) * 4;                               \
            const float* src;                                                   \
            if (row < 128)      src = A   + (long)(m0 + row)       * K + koff + kc; \
            else if (row < 256) src = B1T + (long)(n0 + row - 128) * K + koff + kc; \
            else                src = B2T + (long)(n0 + row - 256) * K + koff + kc; \
            CPA16(base + (row * ASTRIDE + kc) * 4, src);                        \
        }                                                                       \
        CPA_COMMIT();                                                           \
    }

    #pragma unroll
    for (int ps = 0; ps < DSTAGES - 1; ps++) DLOAD(ps, ps);

    for (int kt = 0; kt < NK; kt++) {
        CPA_WAITG(DSTAGES - 2);
        __syncthreads();
        const float* As = sm + (kt % DSTAGES) * DSTAGE_FLOATS;
        const float* B1s = As + BM * ASTRIDE;
        const float* B2s = B1s + BN * ASTRIDE;
        #pragma unroll
        for (int ks = 0; ks < 4; ks++) {
            const int k0 = ks * 8;
            float af[4][4], bf1[4][2], bf2[4][2];
            #pragma unroll
            for (int i = 0; i < 4; i++) {
                const float* ap = As + (wm*64 + i*16 + (lane>>2)) * ASTRIDE + k0 + (lane&3);
                af[i][0] = ap[0];
                af[i][1] = ap[8*ASTRIDE];
                af[i][2] = ap[4];
                af[i][3] = ap[8*ASTRIDE + 4];
            }
            #pragma unroll
            for (int j = 0; j < 4; j++) {
                const float* bp1 = B1s + (wn*32 + j*8 + (lane>>2)) * ASTRIDE + k0 + (lane&3);
                const float* bp2 = B2s + (wn*32 + j*8 + (lane>>2)) * ASTRIDE + k0 + (lane&3);
                bf1[j][0] = bp1[0]; bf1[j][1] = bp1[4];
                bf2[j][0] = bp2[0]; bf2[j][1] = bp2[4];
            }
            #pragma unroll
            for (int i = 0; i < 4; i++)
                #pragma unroll
                for (int j = 0; j < 4; j++) {
                    mma8(acc1[i][j], af[i], bf1[j]);
                    mma8(acc2[i][j], af[i], bf2[j]);
                }
        }
        int nxt = kt + DSTAGES - 1;
        if (nxt < NK) DLOAD(nxt % DSTAGES, nxt)
        else CPA_COMMIT();
    }
    __syncthreads();   // reuse smem for epilogue

    if (MODE == M_FF) {
        #pragma unroll
        for (int i = 0; i < 4; i++) {
            #pragma unroll
            for (int j = 0; j < 4; j++) {
                int r0 = m0 + wm*64 + i*16 + (lane>>2);
                int c0 = n0 + wn*32 + j*8 + 2*(lane&3);
                long o0 = (long)r0 * DFF + c0;
                long o1 = o0 + (long)8 * DFF;
                float a0 = acc1[i][j][0], a1 = acc1[i][j][1];
                float a2 = acc1[i][j][2], a3 = acc1[i][j][3];
                float v0 = tf32r(a0 / (1.f + __expf(-a0)) * acc2[i][j][0]);
                float v1 = tf32r(a1 / (1.f + __expf(-a1)) * acc2[i][j][1]);
                float v2 = tf32r(a2 / (1.f + __expf(-a2)) * acc2[i][j][2]);
                float v3 = tf32r(a3 / (1.f + __expf(-a3)) * acc2[i][j][3]);
                *(float2*)(O1 + o0) = make_float2(v0, v1);
                *(float2*)(O1 + o1) = make_float2(v2, v3);
            }
        }
    } else {
        // gates: activations in-register, transpose via smem, write [b,n,t]
        float* patchG = sm + wid * 2 * (32 * 65);
        float* patchH = patchG + 32 * 65;
        #pragma unroll
        for (int i = 0; i < 4; i++) {
            #pragma unroll
            for (int j = 0; j < 4; j++) {
                int r0 = i*16 + (lane>>2);            // t-local
                int c0 = j*8 + 2*(lane&3);            // n-local
                int n  = n0 + wn*32 + c0;
                float b1a = bias1[n], b1b = bias1[n+1];
                float b2a = bias2[n], b2b = bias2[n+1];
                float g0 = 1.f / (1.f + __expf(-(acc1[i][j][0] + b1a)));
                float g1 = 1.f / (1.f + __expf(-(acc1[i][j][1] + b1b)));
                float g2 = 1.f / (1.f + __expf(-(acc1[i][j][2] + b1a)));
                float g3 = 1.f / (1.f + __expf(-(acc1[i][j][3] + b1b)));
                float h0 = (1.f - g0) * tanhf(acc2[i][j][0] + b2a);
                float h1 = (1.f - g1) * tanhf(acc2[i][j][1] + b2b);
                float h2 = (1.f - g2) * tanhf(acc2[i][j][2] + b2a);
                float h3 = (1.f - g3) * tanhf(acc2[i][j][3] + b2b);
                patchG[c0*65 + r0]       = g0;
                patchG[(c0+1)*65 + r0]   = g1;
                patchG[c0*65 + r0+8]     = g2;
                patchG[(c0+1)*65 + r0+8] = g3;
                patchH[c0*65 + r0]       = h0;
                patchH[(c0+1)*65 + r0]   = h1;
                patchH[c0*65 + r0+8]     = h2;
                patchH[(c0+1)*65 + r0+8] = h3;
            }
        }
        __syncwarp();
        int tokb = m0 + wm * 64;
        int b = tokb >> 12, tb = tokb & 4095;
        #pragma unroll 4
        for (int r = 0; r < 32; r++) {
            int n = n0 + wn*32 + r;
            long off = ((long)(b * DMODEL + n)) * SEQ + tb + lane*2;
            float2 g = make_float2(patchG[r*65 + lane*2], patchG[r*65 + lane*2 + 1]);
            float2 h = make_float2(patchH[r*65 + lane*2], patchH[r*65 + lane*2 + 1]);
            *(float2*)(O1 + off) = g;
            *(float2*)(O2 + off) = h;
        }
    }
    #undef DLOAD
}

// ------------------------- single-B GEMM: O += A@BT^T (residual) -----------
__global__ __launch_bounds__(256, 1) void gemm_res(
    const float* __restrict__ A, const float* __restrict__ BT,
    float* __restrict__ O, int K, int ldo)
{
    extern __shared__ float sm[];
    const uint32_t sbase = smem_u32(sm);
    const int tid = threadIdx.x, lane = tid & 31, wid = tid >> 5;
    const int wm = wid & 1, wn = wid >> 1;
    const int m0 = blockIdx.y * BM, n0 = blockIdx.x * BN;
    const int NK = K / BKK;

    float acc[4][4][4] = {};

    #define SLOAD(stage, ktile)                                                 \
    {                                                                           \
        uint32_t abase = sbase + (stage) * SSTAGE_FLOATS * 4;                   \
        uint32_t bbase = abase + BM * ASTRIDE * 4;                              \
        long koff = (long)(ktile) * BKK;                                        \
        _Pragma("unroll")                                                       \
        for (int i = 0; i < 4; i++) {                                           \
            int id = tid + i * 256;                                             \
            int row = id >> 3, kc = (id & 7) * 4;                               \
            CPA16(abase + (row * ASTRIDE + kc) * 4, A  + (long)(m0+row) * K + koff + kc); \
            CPA16(bbase + (row * ASTRIDE + kc) * 4, BT + (long)(n0+row) * K + koff + kc); \
        }                                                                       \
        CPA_COMMIT();                                                           \
    }

    #pragma unroll
    for (int ps = 0; ps < SSTAGES - 1; ps++) SLOAD(ps, ps);

    for (int kt = 0; kt < NK; kt++) {
        CPA_WAITG(SSTAGES - 2);
        __syncthreads();
        const float* As = sm + (kt % SSTAGES) * SSTAGE_FLOATS;
        const float* Bs = As + BM * ASTRIDE;
        #pragma unroll
        for (int ks = 0; ks < 4; ks++) {
            const int k0 = ks * 8;
            float af[4][4], bf[4][2];
            #pragma unroll
            for (int i = 0; i < 4; i++) {
                const float* ap = As + (wm*64 + i*16 + (lane>>2)) * ASTRIDE + k0 + (lane&3);
                af[i][0] = ap[0];
                af[i][1] = ap[8*ASTRIDE];
                af[i][2] = ap[4];
                af[i][3] = ap[8*ASTRIDE + 4];
            }
            #pragma unroll
            for (int j = 0; j < 4; j++) {
                const float* bp = Bs + (wn*32 + j*8 + (lane>>2)) * ASTRIDE + k0 + (lane&3);
                bf[j][0] = bp[0];
                bf[j][1] = bp[4];
            }
            #pragma unroll
            for (int i = 0; i < 4; i++)
                #pragma unroll
                for (int j = 0; j < 4; j++)
                    mma8(acc[i][j], af[i], bf[j]);
        }
        int nxt = kt + SSTAGES - 1;
        if (nxt < NK) SLOAD(nxt % SSTAGES, nxt)
        else CPA_COMMIT();
    }

    #pragma unroll
    for (int i = 0; i < 4; i++) {
        #pragma unroll
        for (int j = 0; j < 4; j++) {
            int r0 = m0 + wm*64 + i*16 + (lane>>2);
            int c0 = n0 + wn*32 + j*8 + 2*(lane&3);
            long o0 = (long)r0 * ldo + c0;
            long o1 = o0 + (long)8 * ldo;
            float2 p0 = *(const float2*)(O + o0);
            float2 p1 = *(const float2*)(O + o1);
            *(float2*)(O + o0) = make_float2(acc[i][j][0] + p0.x, acc[i][j][1] + p0.y);
            *(float2*)(O + o1) = make_float2(acc[i][j][2] + p1.x, acc[i][j][3] + p1.y);
        }
    }
    #undef SLOAD
}

// ------------------------- RMSNorm (tf32-rounded output) -------------------
__global__ __launch_bounds__(256) void rmsnorm_kernel(
    const float* __restrict__ x, const float* __restrict__ w, float* __restrict__ y)
{
    int row = blockIdx.x, tid = threadIdx.x;
    float4 v = ((const float4*)(x + (long)row * DMODEL))[tid];
    float ss = v.x*v.x + v.y*v.y + v.z*v.z + v.w*v.w;
    #pragma unroll
    for (int o = 16; o; o >>= 1) ss += __shfl_xor_sync(0xffffffffu, ss, o);
    __shared__ float sred[8];
    if ((tid & 31) == 0) sred[tid >> 5] = ss;
    __syncthreads();
    if (tid < 8) {
        float t = sred[tid];
        #pragma unroll
        for (int o = 4; o; o >>= 1) t += __shfl_xor_sync(0xffu, t, o);
        if (tid == 0) sred[0] = t;
    }
    __syncthreads();
    float scale = rsqrtf(sred[0] * (1.0f / DMODEL) + 1e-6f);
    float4 wv = ((const float4*)w)[tid];
    float4 o4 = make_float4(tf32r(v.x*scale*wv.x), tf32r(v.y*scale*wv.y),
                            tf32r(v.z*scale*wv.z), tf32r(v.w*scale*wv.w));
    ((float4*)(y + (long)row * DMODEL))[tid] = o4;
}

// ------------------------- weight transpose + tf32 round -------------------
__global__ void transpose_tf32(const float* __restrict__ W, float* __restrict__ WT,
                               int K, int N)
{
    __shared__ float s[32][33];
    int n0 = blockIdx.x * 32, k0 = blockIdx.y * 32;
    int tx = threadIdx.x, ty = threadIdx.y;
    #pragma unroll
    for (int i = 0; i < 4; i++)
        s[ty + i * 8][tx] = W[(long)(k0 + ty + i * 8) * N + n0 + tx];
    __syncthreads();
    #pragma unroll
    for (int i = 0; i < 4; i++)
        WT[(long)(n0 + ty + i * 8) * K + k0 + tx] = tf32r(s[tx][ty + i * 8]);
}

// ------------------------- scan over t (per (b,d) row) ---------------------
__global__ __launch_bounds__(256) void scan_kernel(
    const float* __restrict__ at, float* __restrict__ bt)
{
    long base = (long)blockIdx.x * SEQ;
    int tid = threadIdx.x;
    float la[16], lb[16];
    const float4* ap = (const float4*)(at + base) + tid * 4;
    float4*       bp = (float4*)(bt + base) + tid * 4;
    #pragma unroll
    for (int q = 0; q < 4; q++) { ((float4*)la)[q] = ap[q]; ((float4*)lb)[q] = bp[q]; }
    float A = 1.f, Bc = 0.f;
    #pragma unroll
    for (int j = 0; j < 16; j++) { Bc = la[j] * Bc + lb[j]; A *= la[j]; }
    __shared__ float sA[256], sB[256];
    sA[tid] = A; sB[tid] = Bc;
    __syncthreads();
    #pragma unroll
    for (int off = 1; off < 256; off <<= 1) {
        float pA = 1.f, pB = 0.f;
        if (tid >= off) { pA = sA[tid - off]; pB = sB[tid - off]; }
        float cA = sA[tid], cB = sB[tid];
        __syncthreads();
        sA[tid] = pA * cA;
        sB[tid] = cA * pB + cB;
        __syncthreads();
    }
    float carry = (tid > 0) ? sB[tid - 1] : 0.f;
    #pragma unroll
    for (int j = 0; j < 16; j++) { carry = la[j] * carry + lb[j]; lb[j] = carry; }
    #pragma unroll
    for (int q = 0; q < 4; q++) bp[q] = ((float4*)lb)[q];
}

// ------------------------- y[b,t,d] = x[b,t,d] + h[b,d,t] ------------------
__global__ void residual_add_t(
    const float* __restrict__ x, const float* __restrict__ ht, float* __restrict__ y)
{
    __shared__ float s[32][33];
    int t0 = blockIdx.x * 32, d0 = blockIdx.y * 32, bb = blockIdx.z;
    int tx = threadIdx.x, ty = threadIdx.y;
    #pragma unroll
    for (int i = 0; i < 4; i++)
        s[ty + i * 8][tx] = ht[((long)(bb * DMODEL + d0 + ty + i * 8)) * SEQ + t0 + tx];
    __syncthreads();
    #pragma unroll
    for (int i = 0; i < 4; i++) {
        long idx = ((long)(bb * SEQ + t0 + ty + i * 8)) * DMODEL + d0 + tx;
        y[idx] = x[idx] + s[tx][ty + i * 8];
    }
}

// ----------------------------------------------------------------------------
extern "C" void kernel_launch(void* const* d_in, const int* in_sizes, int n_in,
                              void* d_out, int out_size)
{
    const float* x   = (const float*)d_in[0];
    const float* Wg  = (const float*)d_in[1];
    const float* bg  = (const float*)d_in[2];
    const float* Wc  = (const float*)d_in[3];
    const float* bc  = (const float*)d_in[4];
    const float* n1w = (const float*)d_in[5];
    const float* n2w = (const float*)d_in[6];
    const float* W1  = (const float*)d_in[7];
    const float* W3  = (const float*)d_in[8];
    const float* W2  = (const float*)d_in[9];
    float* out = (float*)d_out;

    float *hin, *fin, *at, *bt, *u, *WgT, *WcT, *W1T, *W3T, *W2T;
    cudaGetSymbolAddress((void**)&hin, g_hin);
    cudaGetSymbolAddress((void**)&fin, g_fin);
    cudaGetSymbolAddress((void**)&at,  g_at);
    cudaGetSymbolAddress((void**)&bt,  g_bt);
    cudaGetSymbolAddress((void**)&u,   g_u);
    cudaGetSymbolAddress((void**)&WgT, g_WgT);
    cudaGetSymbolAddress((void**)&WcT, g_WcT);
    cudaGetSymbolAddress((void**)&W1T, g_W1T);
    cudaGetSymbolAddress((void**)&W3T, g_W3T);
    cudaGetSymbolAddress((void**)&W2T, g_W2T);

    cudaFuncSetAttribute(gemm_dual<M_GATES>, cudaFuncAttributeMaxDynamicSharedMemorySize, DSMEM);
    cudaFuncSetAttribute(gemm_dual<M_FF>,    cudaFuncAttributeMaxDynamicSharedMemorySize, DSMEM);
    cudaFuncSetAttribute(gemm_res,           cudaFuncAttributeMaxDynamicSharedMemorySize, SSMEM);

    // 0) weight transposes to [N,K] + tf32 rounding
    transpose_tf32<<<dim3(DMODEL/32, DMODEL/32), dim3(32, 8)>>>(Wg, WgT, DMODEL, DMODEL);
    transpose_tf32<<<dim3(DMODEL/32, DMODEL/32), dim3(32, 8)>>>(Wc, WcT, DMODEL, DMODEL);
    transpose_tf32<<<dim3(DFF/32,    DMODEL/32), dim3(32, 8)>>>(W1, W1T, DMODEL, DFF);
    transpose_tf32<<<dim3(DFF/32,    DMODEL/32), dim3(32, 8)>>>(W3, W3T, DMODEL, DFF);
    transpose_tf32<<<dim3(DMODEL/32, DFF/32),    dim3(32, 8)>>>(W2, W2T, DFF, DMODEL);

    // 1) h_in = rmsnorm(x, n1_w)
    rmsnorm_kernel<<<MTOK, 256>>>(x, n1w, hin);

    // 2) dual gates GEMM -> at = sigmoid(.), bt = (1-g)*tanh(.) in [b,d,t]
    gemm_dual<M_GATES><<<dim3(DMODEL/BN, MTOK/BM), 256, DSMEM>>>(
        hin, WgT, WcT, at, bt, bg, bc, DMODEL);

    // 3) linear-recurrence scan along t (in place in bt)
    scan_kernel<<<BATCH * DMODEL, 256>>>(at, bt);

    // 4) x2 = x + h -> out
    residual_add_t<<<dim3(SEQ/32, DMODEL/32, BATCH), dim3(32, 8)>>>(x, bt, out);

    // 5) f_in = rmsnorm(x2, n2_w)
    rmsnorm_kernel<<<MTOK, 256>>>(out, n2w, fin);

    // 6) dual FF GEMM -> u = tf32(silu(fin@W1T) * (fin@W3T))
    gemm_dual<M_FF><<<dim3(DFF/BN, MTOK/BM), 256, DSMEM>>>(
        fin, W1T, W3T, u, nullptr, nullptr, nullptr, DMODEL);

    // 7) out = x2 + u@W2T (residual fused)
    gemm_res<<<dim3(DMODEL/BN, MTOK/BM), 256, SSMEM>>>(u, W2T, out, DFF, DMODEL);
}

// round 5
// speedup vs baseline: 6.4717x; 1.6523x over previous
#include <cuda_runtime.h>
#include <cuda_fp16.h>
#include <math.h>
#include <stdint.h>

#define BATCH 4
#define SEQ   4096
#define DMODEL 1024
#define DFF   4096
#define MTOK  (BATCH*SEQ)

// GEMM tiling
#define BM 128
#define BN 128
#define BKK 32
#define HSTRIDE 40                                   // halfs per smem row (32+8 pad)

// dual-B kernel: 4 stages
#define DSTAGES 4
#define DSTAGE_HALFS ((BM + 2*BN) * HSTRIDE)         // 15360 halfs = 30720B
#define DSMEM 133120                                 // max(stages, gates patch)

// single-B (W2): 4 stages, 2 CTAs/SM
#define SSTAGES 4
#define SSTAGE_HALFS ((BM + BN) * HSTRIDE)           // 10240 halfs = 20480B
#define SSMEM (SSTAGES * SSTAGE_HALFS * 2)           // 81920

#define M_GATES 0
#define M_FF    1

// ------------------------- scratch -----------------------------------------
__device__ __half g_hin[MTOK*DMODEL];
__device__ __half g_fin[MTOK*DMODEL];
__device__ float  g_at [BATCH*DMODEL*SEQ];
__device__ float  g_bt [BATCH*DMODEL*SEQ];
__device__ __half g_u  [(size_t)MTOK*DFF];
__device__ __half g_WgT[DMODEL*DMODEL];
__device__ __half g_WcT[DMODEL*DMODEL];
__device__ __half g_W1T[(size_t)DFF*DMODEL];
__device__ __half g_W3T[(size_t)DFF*DMODEL];
__device__ __half g_W2T[(size_t)DMODEL*DFF];

// ------------------------- helpers -----------------------------------------
__device__ __forceinline__ uint32_t smem_u32(const void* p) {
    uint32_t a;
    asm("{ .reg .u64 t; cvta.to.shared.u64 t, %1; cvt.u32.u64 %0, t; }"
        : "=r"(a) : "l"(p));
    return a;
}
#define CPA16(dst, src) \
    asm volatile("cp.async.cg.shared.global [%0], [%1], 16;" :: "r"(dst), "l"(src))
#define CPA_COMMIT() asm volatile("cp.async.commit_group;" ::: "memory")
#define CPA_WAITG(n) asm volatile("cp.async.wait_group %0;" :: "n"(n) : "memory")

__device__ __forceinline__ void hmma(float c[4], const uint32_t a[4], const uint32_t b[2]) {
    asm volatile(
        "mma.sync.aligned.m16n8k16.row.col.f32.f16.f16.f32 "
        "{%0,%1,%2,%3},{%4,%5,%6,%7},{%8,%9},{%0,%1,%2,%3};"
        : "+f"(c[0]), "+f"(c[1]), "+f"(c[2]), "+f"(c[3])
        : "r"(a[0]), "r"(a[1]), "r"(a[2]), "r"(a[3]), "r"(b[0]), "r"(b[1]));
}
__device__ __forceinline__ uint32_t ldh2(const __half* p) {
    return *(const uint32_t*)p;
}

// ------------------------- dual-B fp16 tensor-core GEMM --------------------
// acc1 = A@B1T^T, acc2 = A@B2T^T, shared A pipeline. fp32 accumulate.
// M_GATES: at[b,n,t]=sigmoid(acc1+bg[n]); bt[b,n,t]=(1-g)*tanh(acc2+bc[n])
// M_FF:    U[tok,DFF] = half(silu(acc1) * acc2)
template<int MODE>
__global__ __launch_bounds__(256, 1) void gemm_dual(
    const __half* __restrict__ A, const __half* __restrict__ B1T,
    const __half* __restrict__ B2T,
    float* __restrict__ O1, float* __restrict__ O2, __half* __restrict__ OU,
    const float* __restrict__ bias1, const float* __restrict__ bias2,
    int K)
{
    extern __shared__ __half smh[];
    const uint32_t sbase = smem_u32(smh);
    const int tid = threadIdx.x, lane = tid & 31, wid = tid >> 5;
    const int wm = wid & 1, wn = wid >> 1;     // warp tile 64(m) x 32(n) per output
    const int m0 = blockIdx.y * BM, n0 = blockIdx.x * BN;
    const int NK = K / BKK;

    float acc1[4][4][4] = {};
    float acc2[4][4][4] = {};

    // 6 cp16 per thread per stage (384 rows x 4 chunks of 8 halfs)
    #define DLOAD(stage, ktile)                                                   \
    {                                                                             \
        uint32_t base = sbase + (stage) * DSTAGE_HALFS * 2;                       \
        long koff = (long)(ktile) * BKK;                                          \
        _Pragma("unroll")                                                         \
        for (int i = 0; i < 6; i++) {                                             \
            int id = tid + i * 256;                                               \
            int row = id >> 2, ch = (id & 3) * 8;                                 \
            const __half* src;                                                    \
            if (row < 128)      src = A   + (long)(m0 + row)       * K + koff + ch; \
            else if (row < 256) src = B1T + (long)(n0 + row - 128) * K + koff + ch; \
            else                src = B2T + (long)(n0 + row - 256) * K + koff + ch; \
            CPA16(base + (row * HSTRIDE + ch) * 2, src);                          \
        }                                                                         \
        CPA_COMMIT();                                                             \
    }

    #pragma unroll
    for (int ps = 0; ps < DSTAGES - 1; ps++) DLOAD(ps, ps);

    for (int kt = 0; kt < NK; kt++) {
        CPA_WAITG(DSTAGES - 2);
        __syncthreads();
        const __half* As  = smh + (kt % DSTAGES) * DSTAGE_HALFS;
        const __half* B1s = As + BM * HSTRIDE;
        const __half* B2s = B1s + BN * HSTRIDE;
        #pragma unroll
        for (int ks = 0; ks < 2; ks++) {
            const int k0 = ks * 16 + 2 * (lane & 3);
            uint32_t af[4][4], bf1[4][2], bf2[4][2];
            #pragma unroll
            for (int i = 0; i < 4; i++) {
                const __half* ap = As + (wm*64 + i*16 + (lane>>2)) * HSTRIDE + k0;
                af[i][0] = ldh2(ap);
                af[i][1] = ldh2(ap + 8*HSTRIDE);
                af[i][2] = ldh2(ap + 8);
                af[i][3] = ldh2(ap + 8*HSTRIDE + 8);
            }
            #pragma unroll
            for (int j = 0; j < 4; j++) {
                const __half* bp1 = B1s + (wn*32 + j*8 + (lane>>2)) * HSTRIDE + k0;
                const __half* bp2 = B2s + (wn*32 + j*8 + (lane>>2)) * HSTRIDE + k0;
                bf1[j][0] = ldh2(bp1); bf1[j][1] = ldh2(bp1 + 8);
                bf2[j][0] = ldh2(bp2); bf2[j][1] = ldh2(bp2 + 8);
            }
            #pragma unroll
            for (int i = 0; i < 4; i++)
                #pragma unroll
                for (int j = 0; j < 4; j++) {
                    hmma(acc1[i][j], af[i], bf1[j]);
                    hmma(acc2[i][j], af[i], bf2[j]);
                }
        }
        int nxt = kt + DSTAGES - 1;
        if (nxt < NK) DLOAD(nxt % DSTAGES, nxt)
        else CPA_COMMIT();
    }
    __syncthreads();   // reuse smem for epilogue

    if (MODE == M_FF) {
        #pragma unroll
        for (int i = 0; i < 4; i++) {
            #pragma unroll
            for (int j = 0; j < 4; j++) {
                int r0 = m0 + wm*64 + i*16 + (lane>>2);
                int c0 = n0 + wn*32 + j*8 + 2*(lane&3);
                long o0 = (long)r0 * DFF + c0;
                long o1 = o0 + (long)8 * DFF;
                float a0 = acc1[i][j][0], a1 = acc1[i][j][1];
                float a2 = acc1[i][j][2], a3 = acc1[i][j][3];
                float v0 = a0 / (1.f + __expf(-a0)) * acc2[i][j][0];
                float v1 = a1 / (1.f + __expf(-a1)) * acc2[i][j][1];
                float v2 = a2 / (1.f + __expf(-a2)) * acc2[i][j][2];
                float v3 = a3 / (1.f + __expf(-a3)) * acc2[i][j][3];
                *(__half2*)(OU + o0) = __floats2half2_rn(v0, v1);
                *(__half2*)(OU + o1) = __floats2half2_rn(v2, v3);
            }
        }
    } else {
        float* patchG = (float*)smh + wid * 2 * (32 * 65);
        float* patchH = patchG + 32 * 65;
        #pragma unroll
        for (int i = 0; i < 4; i++) {
            #pragma unroll
            for (int j = 0; j < 4; j++) {
                int r0 = i*16 + (lane>>2);            // t-local
                int c0 = j*8 + 2*(lane&3);            // n-local
                int n  = n0 + wn*32 + c0;
                float b1a = bias1[n], b1b = bias1[n+1];
                float b2a = bias2[n], b2b = bias2[n+1];
                float g0 = 1.f / (1.f + __expf(-(acc1[i][j][0] + b1a)));
                float g1 = 1.f / (1.f + __expf(-(acc1[i][j][1] + b1b)));
                float g2 = 1.f / (1.f + __expf(-(acc1[i][j][2] + b1a)));
                float g3 = 1.f / (1.f + __expf(-(acc1[i][j][3] + b1b)));
                float h0 = (1.f - g0) * tanhf(acc2[i][j][0] + b2a);
                float h1 = (1.f - g1) * tanhf(acc2[i][j][1] + b2b);
                float h2 = (1.f - g2) * tanhf(acc2[i][j][2] + b2a);
                float h3 = (1.f - g3) * tanhf(acc2[i][j][3] + b2b);
                patchG[c0*65 + r0]       = g0;
                patchG[(c0+1)*65 + r0]   = g1;
                patchG[c0*65 + r0+8]     = g2;
                patchG[(c0+1)*65 + r0+8] = g3;
                patchH[c0*65 + r0]       = h0;
                patchH[(c0+1)*65 + r0]   = h1;
                patchH[c0*65 + r0+8]     = h2;
                patchH[(c0+1)*65 + r0+8] = h3;
            }
        }
        __syncwarp();
        int tokb = m0 + wm * 64;
        int b = tokb >> 12, tb = tokb & 4095;
        #pragma unroll 4
        for (int r = 0; r < 32; r++) {
            int n = n0 + wn*32 + r;
            long off = ((long)(b * DMODEL + n)) * SEQ + tb + lane*2;
            float2 g = make_float2(patchG[r*65 + lane*2], patchG[r*65 + lane*2 + 1]);
            float2 h = make_float2(patchH[r*65 + lane*2], patchH[r*65 + lane*2 + 1]);
            *(float2*)(O1 + off) = g;
            *(float2*)(O2 + off) = h;
        }
    }
    #undef DLOAD
}

// ------------------------- single-B fp16 GEMM: O += A@BT^T -----------------
__global__ __launch_bounds__(256, 2) void gemm_res(
    const __half* __restrict__ A, const __half* __restrict__ BT,
    float* __restrict__ O, int K, int ldo)
{
    extern __shared__ __half smh[];
    const uint32_t sbase = smem_u32(smh);
    const int tid = threadIdx.x, lane = tid & 31, wid = tid >> 5;
    const int wm = wid & 1, wn = wid >> 1;
    const int m0 = blockIdx.y * BM, n0 = blockIdx.x * BN;
    const int NK = K / BKK;

    float acc[4][4][4] = {};

    #define SLOAD(stage, ktile)                                                   \
    {                                                                             \
        uint32_t base = sbase + (stage) * SSTAGE_HALFS * 2;                       \
        long koff = (long)(ktile) * BKK;                                          \
        _Pragma("unroll")                                                         \
        for (int i = 0; i < 4; i++) {                                             \
            int id = tid + i * 256;                                               \
            int row = id >> 2, ch = (id & 3) * 8;                                 \
            const __half* src;                                                    \
            if (row < 128) src = A  + (long)(m0 + row)       * K + koff + ch;     \
            else           src = BT + (long)(n0 + row - 128) * K + koff + ch;     \
            CPA16(base + (row * HSTRIDE + ch) * 2, src);                          \
        }                                                                         \
        CPA_COMMIT();                                                             \
    }

    #pragma unroll
    for (int ps = 0; ps < SSTAGES - 1; ps++) SLOAD(ps, ps);

    for (int kt = 0; kt < NK; kt++) {
        CPA_WAITG(SSTAGES - 2);
        __syncthreads();
        const __half* As = smh + (kt % SSTAGES) * SSTAGE_HALFS;
        const __half* Bs = As + BM * HSTRIDE;
        #pragma unroll
        for (int ks = 0; ks < 2; ks++) {
            const int k0 = ks * 16 + 2 * (lane & 3);
            uint32_t af[4][4], bf[4][2];
            #pragma unroll
            for (int i = 0; i < 4; i++) {
                const __half* ap = As + (wm*64 + i*16 + (lane>>2)) * HSTRIDE + k0;
                af[i][0] = ldh2(ap);
                af[i][1] = ldh2(ap + 8*HSTRIDE);
                af[i][2] = ldh2(ap + 8);
                af[i][3] = ldh2(ap + 8*HSTRIDE + 8);
            }
            #pragma unroll
            for (int j = 0; j < 4; j++) {
                const __half* bp = Bs + (wn*32 + j*8 + (lane>>2)) * HSTRIDE + k0;
                bf[j][0] = ldh2(bp); bf[j][1] = ldh2(bp + 8);
            }
            #pragma unroll
            for (int i = 0; i < 4; i++)
                #pragma unroll
                for (int j = 0; j < 4; j++)
                    hmma(acc[i][j], af[i], bf[j]);
        }
        int nxt = kt + SSTAGES - 1;
        if (nxt < NK) SLOAD(nxt % SSTAGES, nxt)
        else CPA_COMMIT();
    }

    #pragma unroll
    for (int i = 0; i < 4; i++) {
        #pragma unroll
        for (int j = 0; j < 4; j++) {
            int r0 = m0 + wm*64 + i*16 + (lane>>2);
            int c0 = n0 + wn*32 + j*8 + 2*(lane&3);
            long o0 = (long)r0 * ldo + c0;
            long o1 = o0 + (long)8 * ldo;
            float2 p0 = *(const float2*)(O + o0);
            float2 p1 = *(const float2*)(O + o1);
            *(float2*)(O + o0) = make_float2(acc[i][j][0] + p0.x, acc[i][j][1] + p0.y);
            *(float2*)(O + o1) = make_float2(acc[i][j][2] + p1.x, acc[i][j][3] + p1.y);
        }
    }
    #undef SLOAD
}

// ------------------------- RMSNorm -> fp16 output --------------------------
__global__ __launch_bounds__(256) void rmsnorm_h(
    const float* __restrict__ x, const float* __restrict__ w, __half* __restrict__ y)
{
    int row = blockIdx.x, tid = threadIdx.x;
    float4 v = ((const float4*)(x + (long)row * DMODEL))[tid];
    float ss = v.x*v.x + v.y*v.y + v.z*v.z + v.w*v.w;
    #pragma unroll
    for (int o = 16; o; o >>= 1) ss += __shfl_xor_sync(0xffffffffu, ss, o);
    __shared__ float sred[8];
    if ((tid & 31) == 0) sred[tid >> 5] = ss;
    __syncthreads();
    if (tid < 8) {
        float t = sred[tid];
        #pragma unroll
        for (int o = 4; o; o >>= 1) t += __shfl_xor_sync(0xffu, t, o);
        if (tid == 0) sred[0] = t;
    }
    __syncthreads();
    float scale = rsqrtf(sred[0] * (1.0f / DMODEL) + 1e-6f);
    float4 wv = ((const float4*)w)[tid];
    __half2 h01 = __floats2half2_rn(v.x*scale*wv.x, v.y*scale*wv.y);
    __half2 h23 = __floats2half2_rn(v.z*scale*wv.z, v.w*scale*wv.w);
    __half2* yp = (__half2*)(y + (long)row * DMODEL) + tid * 2;
    yp[0] = h01; yp[1] = h23;
}

// ------------------------- weight transpose -> fp16 ------------------------
__global__ void transpose_h(const float* __restrict__ W, __half* __restrict__ WT,
                            int K, int N)
{
    __shared__ float s[32][33];
    int n0 = blockIdx.x * 32, k0 = blockIdx.y * 32;
    int tx = threadIdx.x, ty = threadIdx.y;
    #pragma unroll
    for (int i = 0; i < 4; i++)
        s[ty + i * 8][tx] = W[(long)(k0 + ty + i * 8) * N + n0 + tx];
    __syncthreads();
    #pragma unroll
    for (int i = 0; i < 4; i++)
        WT[(long)(n0 + ty + i * 8) * K + k0 + tx] = __float2half_rn(s[tx][ty + i * 8]);
}

// ------------------------- scan over t (per (b,d) row) ---------------------
__global__ __launch_bounds__(256) void scan_kernel(
    const float* __restrict__ at, float* __restrict__ bt)
{
    long base = (long)blockIdx.x * SEQ;
    int tid = threadIdx.x;
    float la[16], lb[16];
    const float4* ap = (const float4*)(at + base) + tid * 4;
    float4*       bp = (float4*)(bt + base) + tid * 4;
    #pragma unroll
    for (int q = 0; q < 4; q++) { ((float4*)la)[q] = ap[q]; ((float4*)lb)[q] = bp[q]; }
    float A = 1.f, Bc = 0.f;
    #pragma unroll
    for (int j = 0; j < 16; j++) { Bc = la[j] * Bc + lb[j]; A *= la[j]; }
    __shared__ float sA[256], sB[256];
    sA[tid] = A; sB[tid] = Bc;
    __syncthreads();
    #pragma unroll
    for (int off = 1; off < 256; off <<= 1) {
        float pA = 1.f, pB = 0.f;
        if (tid >= off) { pA = sA[tid - off]; pB = sB[tid - off]; }
        float cA = sA[tid], cB = sB[tid];
        __syncthreads();
        sA[tid] = pA * cA;
        sB[tid] = cA * pB + cB;
        __syncthreads();
    }
    float carry = (tid > 0) ? sB[tid - 1] : 0.f;
    #pragma unroll
    for (int j = 0; j < 16; j++) { carry = la[j] * carry + lb[j]; lb[j] = carry; }
    #pragma unroll
    for (int q = 0; q < 4; q++) bp[q] = ((float4*)lb)[q];
}

// ------------------------- y[b,t,d] = x[b,t,d] + h[b,d,t] ------------------
__global__ void residual_add_t(
    const float* __restrict__ x, const float* __restrict__ ht, float* __restrict__ y)
{
    __shared__ float s[32][33];
    int t0 = blockIdx.x * 32, d0 = blockIdx.y * 32, bb = blockIdx.z;
    int tx = threadIdx.x, ty = threadIdx.y;
    #pragma unroll
    for (int i = 0; i < 4; i++)
        s[ty + i * 8][tx] = ht[((long)(bb * DMODEL + d0 + ty + i * 8)) * SEQ + t0 + tx];
    __syncthreads();
    #pragma unroll
    for (int i = 0; i < 4; i++) {
        long idx = ((long)(bb * SEQ + t0 + ty + i * 8)) * DMODEL + d0 + tx;
        y[idx] = x[idx] + s[tx][ty + i * 8];
    }
}

// ----------------------------------------------------------------------------
extern "C" void kernel_launch(void* const* d_in, const int* in_sizes, int n_in,
                              void* d_out, int out_size)
{
    const float* x   = (const float*)d_in[0];
    const float* Wg  = (const float*)d_in[1];
    const float* bg  = (const float*)d_in[2];
    const float* Wc  = (const float*)d_in[3];
    const float* bc  = (const float*)d_in[4];
    const float* n1w = (const float*)d_in[5];
    const float* n2w = (const float*)d_in[6];
    const float* W1  = (const float*)d_in[7];
    const float* W3  = (const float*)d_in[8];
    const float* W2  = (const float*)d_in[9];
    float* out = (float*)d_out;

    __half *hin, *fin, *u, *WgT, *WcT, *W1T, *W3T, *W2T;
    float *at, *bt;
    cudaGetSymbolAddress((void**)&hin, g_hin);
    cudaGetSymbolAddress((void**)&fin, g_fin);
    cudaGetSymbolAddress((void**)&at,  g_at);
    cudaGetSymbolAddress((void**)&bt,  g_bt);
    cudaGetSymbolAddress((void**)&u,   g_u);
    cudaGetSymbolAddress((void**)&WgT, g_WgT);
    cudaGetSymbolAddress((void**)&WcT, g_WcT);
    cudaGetSymbolAddress((void**)&W1T, g_W1T);
    cudaGetSymbolAddress((void**)&W3T, g_W3T);
    cudaGetSymbolAddress((void**)&W2T, g_W2T);

    cudaFuncSetAttribute(gemm_dual<M_GATES>, cudaFuncAttributeMaxDynamicSharedMemorySize, DSMEM);
    cudaFuncSetAttribute(gemm_dual<M_FF>,    cudaFuncAttributeMaxDynamicSharedMemorySize, DSMEM);
    cudaFuncSetAttribute(gemm_res,           cudaFuncAttributeMaxDynamicSharedMemorySize, SSMEM);

    // 0) weight transposes to [N,K] fp16
    transpose_h<<<dim3(DMODEL/32, DMODEL/32), dim3(32, 8)>>>(Wg, WgT, DMODEL, DMODEL);
    transpose_h<<<dim3(DMODEL/32, DMODEL/32), dim3(32, 8)>>>(Wc, WcT, DMODEL, DMODEL);
    transpose_h<<<dim3(DFF/32,    DMODEL/32), dim3(32, 8)>>>(W1, W1T, DMODEL, DFF);
    transpose_h<<<dim3(DFF/32,    DMODEL/32), dim3(32, 8)>>>(W3, W3T, DMODEL, DFF);
    transpose_h<<<dim3(DMODEL/32, DFF/32),    dim3(32, 8)>>>(W2, W2T, DFF, DMODEL);

    // 1) h_in = rmsnorm(x, n1_w) -> fp16
    rmsnorm_h<<<MTOK, 256>>>(x, n1w, hin);

    // 2) dual gates GEMM -> at = sigmoid(.), bt = (1-g)*tanh(.) in [b,d,t]
    gemm_dual<M_GATES><<<dim3(DMODEL/BN, MTOK/BM), 256, DSMEM>>>(
        hin, WgT, WcT, at, bt, nullptr, bg, bc, DMODEL);

    // 3) linear-recurrence scan along t (in place in bt)
    scan_kernel<<<BATCH * DMODEL, 256>>>(at, bt);

    // 4) x2 = x + h -> out
    residual_add_t<<<dim3(SEQ/32, DMODEL/32, BATCH), dim3(32, 8)>>>(x, bt, out);

    // 5) f_in = rmsnorm(x2, n2_w) -> fp16
    rmsnorm_h<<<MTOK, 256>>>(out, n2w, fin);

    // 6) dual FF GEMM -> u = half(silu(fin@W1T) * (fin@W3T))
    gemm_dual<M_FF><<<dim3(DFF/BN, MTOK/BM), 256, DSMEM>>>(
        fin, W1T, W3T, nullptr, nullptr, u, nullptr, nullptr, DMODEL);

    // 7) out = x2 + u@W2T (residual fused)
    gemm_res<<<dim3(DMODEL/BN, MTOK/BM), 256, SSMEM>>>(u, W2T, out, DFF, DMODEL);
}

// round 6
// speedup vs baseline: 7.1164x; 1.0996x over previous
#include <cuda_runtime.h>
#include <cuda_fp16.h>
#include <math.h>
#include <stdint.h>

#define BATCH 4
#define SEQ   4096
#define DMODEL 1024
#define DFF   4096
#define MTOK  (BATCH*SEQ)

// GEMM tiling
#define BM 128
#define BN 128
#define BKK 32
#define HSTRIDE 40                                   // halfs per smem row (32+8 pad)

// dual-B kernel: 4 stages
#define DSTAGES 4
#define DSTAGE_HALFS ((BM + 2*BN) * HSTRIDE)         // 15360 halfs = 30720B
#define DSMEM 133120                                 // max(stages, gates patch)

// single-B (W2): 4 stages, 2 CTAs/SM
#define SSTAGES 4
#define SSTAGE_HALFS ((BM + BN) * HSTRIDE)           // 10240 halfs = 20480B
#define SSMEM (SSTAGES * SSTAGE_HALFS * 2)           // 81920

#define M_GATES 0
#define M_FF    1

// ------------------------- scratch -----------------------------------------
__device__ __half g_hin[MTOK*DMODEL];
__device__ __half g_fin[MTOK*DMODEL];
__device__ float  g_at [BATCH*DMODEL*SEQ];
__device__ float  g_bt [BATCH*DMODEL*SEQ];
__device__ __half g_u  [(size_t)MTOK*DFF];
__device__ __half g_WgT[DMODEL*DMODEL];
__device__ __half g_WcT[DMODEL*DMODEL];
__device__ __half g_W1T[(size_t)DFF*DMODEL];
__device__ __half g_W3T[(size_t)DFF*DMODEL];
__device__ __half g_W2T[(size_t)DMODEL*DFF];

// ------------------------- helpers -----------------------------------------
__device__ __forceinline__ uint32_t smem_u32(const void* p) {
    uint32_t a;
    asm("{ .reg .u64 t; cvta.to.shared.u64 t, %1; cvt.u32.u64 %0, t; }"
        : "=r"(a) : "l"(p));
    return a;
}
#define CPA16(dst, src) \
    asm volatile("cp.async.cg.shared.global [%0], [%1], 16;" :: "r"(dst), "l"(src))
#define CPA_COMMIT() asm volatile("cp.async.commit_group;" ::: "memory")
#define CPA_WAITG(n) asm volatile("cp.async.wait_group %0;" :: "n"(n) : "memory")

__device__ __forceinline__ void hmma(float c[4], const uint32_t a[4], const uint32_t b[2]) {
    asm volatile(
        "mma.sync.aligned.m16n8k16.row.col.f32.f16.f16.f32 "
        "{%0,%1,%2,%3},{%4,%5,%6,%7},{%8,%9},{%0,%1,%2,%3};"
        : "+f"(c[0]), "+f"(c[1]), "+f"(c[2]), "+f"(c[3])
        : "r"(a[0]), "r"(a[1]), "r"(a[2]), "r"(a[3]), "r"(b[0]), "r"(b[1]));
}
__device__ __forceinline__ void ldsm4(uint32_t& r0, uint32_t& r1, uint32_t& r2,
                                      uint32_t& r3, uint32_t addr) {
    asm volatile("ldmatrix.sync.aligned.m8n8.x4.shared.b16 {%0,%1,%2,%3}, [%4];"
                 : "=r"(r0), "=r"(r1), "=r"(r2), "=r"(r3) : "r"(addr));
}

// lane-dependent ldmatrix offsets (in halfs, relative to tile base):
//   A x4 (m16 x k16):  rows lane&15, k +8*(lane>>4)
//   B x4 (n16 x k16):  rows (lane&7)+8*(lane>>4), k +8*((lane>>3)&1)
__device__ __forceinline__ int a_lm_off(int lane) {
    return (lane & 15) * HSTRIDE + 8 * (lane >> 4);
}
__device__ __forceinline__ int b_lm_off(int lane) {
    return ((lane & 7) + 8 * (lane >> 4)) * HSTRIDE + 8 * ((lane >> 3) & 1);
}

// ------------------------- dual-B fp16 tensor-core GEMM --------------------
// acc1 = A@B1T^T, acc2 = A@B2T^T, shared A pipeline. fp32 accumulate.
// M_GATES: at[b,n,t]=sigmoid(acc1+bg[n]); bt[b,n,t]=(1-g)*tanh(acc2+bc[n])
// M_FF:    U[tok,DFF] = half(silu(acc1) * acc2)
template<int MODE>
__global__ __launch_bounds__(256, 1) void gemm_dual(
    const __half* __restrict__ A, const __half* __restrict__ B1T,
    const __half* __restrict__ B2T,
    float* __restrict__ O1, float* __restrict__ O2, __half* __restrict__ OU,
    const float* __restrict__ bias1, const float* __restrict__ bias2,
    int K)
{
    extern __shared__ __half smh[];
    const uint32_t sbase = smem_u32(smh);
    const int tid = threadIdx.x, lane = tid & 31, wid = tid >> 5;
    const int wm = wid & 1, wn = wid >> 1;     // warp tile 64(m) x 32(n) per output
    const int m0 = blockIdx.y * BM, n0 = blockIdx.x * BN;
    const int NK = K / BKK;

    const int aoff = a_lm_off(lane);           // halfs
    const int boff = b_lm_off(lane);

    float acc1[4][4][4] = {};
    float acc2[4][4][4] = {};

    #define DLOAD(stage, ktile)                                                   \
    {                                                                             \
        uint32_t base = sbase + (stage) * DSTAGE_HALFS * 2;                       \
        long koff = (long)(ktile) * BKK;                                          \
        _Pragma("unroll")                                                         \
        for (int i = 0; i < 6; i++) {                                             \
            int id = tid + i * 256;                                               \
            int row = id >> 2, ch = (id & 3) * 8;                                 \
            const __half* src;                                                    \
            if (row < 128)      src = A   + (long)(m0 + row)       * K + koff + ch; \
            else if (row < 256) src = B1T + (long)(n0 + row - 128) * K + koff + ch; \
            else                src = B2T + (long)(n0 + row - 256) * K + koff + ch; \
            CPA16(base + (row * HSTRIDE + ch) * 2, src);                          \
        }                                                                         \
        CPA_COMMIT();                                                             \
    }

    #pragma unroll
    for (int ps = 0; ps < DSTAGES - 1; ps++) DLOAD(ps, ps);

    for (int kt = 0; kt < NK; kt++) {
        CPA_WAITG(DSTAGES - 2);
        __syncthreads();
        uint32_t stg = sbase + (kt % DSTAGES) * DSTAGE_HALFS * 2;
        uint32_t As  = stg;
        uint32_t B1s = stg + BM * HSTRIDE * 2;
        uint32_t B2s = stg + (BM + BN) * HSTRIDE * 2;
        #pragma unroll
        for (int ks = 0; ks < 2; ks++) {
            const int k0 = ks * 16;
            uint32_t af[4][4], bf1[4][2], bf2[4][2];
            #pragma unroll
            for (int i = 0; i < 4; i++) {
                uint32_t ad = As + ((wm*64 + i*16) * HSTRIDE + k0 + aoff) * 2;
                ldsm4(af[i][0], af[i][1], af[i][2], af[i][3], ad);
            }
            #pragma unroll
            for (int jp = 0; jp < 2; jp++) {
                uint32_t bd1 = B1s + ((wn*32 + jp*16) * HSTRIDE + k0 + boff) * 2;
                uint32_t bd2 = B2s + ((wn*32 + jp*16) * HSTRIDE + k0 + boff) * 2;
                ldsm4(bf1[jp*2][0], bf1[jp*2][1], bf1[jp*2+1][0], bf1[jp*2+1][1], bd1);
                ldsm4(bf2[jp*2][0], bf2[jp*2][1], bf2[jp*2+1][0], bf2[jp*2+1][1], bd2);
            }
            #pragma unroll
            for (int i = 0; i < 4; i++)
                #pragma unroll
                for (int j = 0; j < 4; j++) {
                    hmma(acc1[i][j], af[i], bf1[j]);
                    hmma(acc2[i][j], af[i], bf2[j]);
                }
        }
        int nxt = kt + DSTAGES - 1;
        if (nxt < NK) DLOAD(nxt % DSTAGES, nxt)
        else CPA_COMMIT();
    }
    __syncthreads();   // reuse smem for epilogue

    if (MODE == M_FF) {
        #pragma unroll
        for (int i = 0; i < 4; i++) {
            #pragma unroll
            for (int j = 0; j < 4; j++) {
                int r0 = m0 + wm*64 + i*16 + (lane>>2);
                int c0 = n0 + wn*32 + j*8 + 2*(lane&3);
                long o0 = (long)r0 * DFF + c0;
                long o1 = o0 + (long)8 * DFF;
                float a0 = acc1[i][j][0], a1 = acc1[i][j][1];
                float a2 = acc1[i][j][2], a3 = acc1[i][j][3];
                float v0 = a0 / (1.f + __expf(-a0)) * acc2[i][j][0];
                float v1 = a1 / (1.f + __expf(-a1)) * acc2[i][j][1];
                float v2 = a2 / (1.f + __expf(-a2)) * acc2[i][j][2];
                float v3 = a3 / (1.f + __expf(-a3)) * acc2[i][j][3];
                *(__half2*)(OU + o0) = __floats2half2_rn(v0, v1);
                *(__half2*)(OU + o1) = __floats2half2_rn(v2, v3);
            }
        }
    } else {
        float* patchG = (float*)smh + wid * 2 * (32 * 65);
        float* patchH = patchG + 32 * 65;
        #pragma unroll
        for (int i = 0; i < 4; i++) {
            #pragma unroll
            for (int j = 0; j < 4; j++) {
                int r0 = i*16 + (lane>>2);            // t-local
                int c0 = j*8 + 2*(lane&3);            // n-local
                int n  = n0 + wn*32 + c0;
                float b1a = bias1[n], b1b = bias1[n+1];
                float b2a = bias2[n], b2b = bias2[n+1];
                float g0 = 1.f / (1.f + __expf(-(acc1[i][j][0] + b1a)));
                float g1 = 1.f / (1.f + __expf(-(acc1[i][j][1] + b1b)));
                float g2 = 1.f / (1.f + __expf(-(acc1[i][j][2] + b1a)));
                float g3 = 1.f / (1.f + __expf(-(acc1[i][j][3] + b1b)));
                float h0 = (1.f - g0) * tanhf(acc2[i][j][0] + b2a);
                float h1 = (1.f - g1) * tanhf(acc2[i][j][1] + b2b);
                float h2 = (1.f - g2) * tanhf(acc2[i][j][2] + b2a);
                float h3 = (1.f - g3) * tanhf(acc2[i][j][3] + b2b);
                patchG[c0*65 + r0]       = g0;
                patchG[(c0+1)*65 + r0]   = g1;
                patchG[c0*65 + r0+8]     = g2;
                patchG[(c0+1)*65 + r0+8] = g3;
                patchH[c0*65 + r0]       = h0;
                patchH[(c0+1)*65 + r0]   = h1;
                patchH[c0*65 + r0+8]     = h2;
                patchH[(c0+1)*65 + r0+8] = h3;
            }
        }
        __syncwarp();
        int tokb = m0 + wm * 64;
        int b = tokb >> 12, tb = tokb & 4095;
        #pragma unroll 4
        for (int r = 0; r < 32; r++) {
            int n = n0 + wn*32 + r;
            long off = ((long)(b * DMODEL + n)) * SEQ + tb + lane*2;
            float2 g = make_float2(patchG[r*65 + lane*2], patchG[r*65 + lane*2 + 1]);
            float2 h = make_float2(patchH[r*65 + lane*2], patchH[r*65 + lane*2 + 1]);
            *(float2*)(O1 + off) = g;
            *(float2*)(O2 + off) = h;
        }
    }
    #undef DLOAD
}

// ------------------------- single-B fp16 GEMM: O += A@BT^T -----------------
__global__ __launch_bounds__(256, 2) void gemm_res(
    const __half* __restrict__ A, const __half* __restrict__ BT,
    float* __restrict__ O, int K, int ldo)
{
    extern __shared__ __half smh[];
    const uint32_t sbase = smem_u32(smh);
    const int tid = threadIdx.x, lane = tid & 31, wid = tid >> 5;
    const int wm = wid & 1, wn = wid >> 1;
    const int m0 = blockIdx.y * BM, n0 = blockIdx.x * BN;
    const int NK = K / BKK;

    const int aoff = a_lm_off(lane);
    const int boff = b_lm_off(lane);

    float acc[4][4][4] = {};

    #define SLOAD(stage, ktile)                                                   \
    {                                                                             \
        uint32_t base = sbase + (stage) * SSTAGE_HALFS * 2;                       \
        long koff = (long)(ktile) * BKK;                                          \
        _Pragma("unroll")                                                         \
        for (int i = 0; i < 4; i++) {                                             \
            int id = tid + i * 256;                                               \
            int row = id >> 2, ch = (id & 3) * 8;                                 \
            const __half* src;                                                    \
            if (row < 128) src = A  + (long)(m0 + row)       * K + koff + ch;     \
            else           src = BT + (long)(n0 + row - 128) * K + koff + ch;     \
            CPA16(base + (row * HSTRIDE + ch) * 2, src);                          \
        }                                                                         \
        CPA_COMMIT();                                                             \
    }

    #pragma unroll
    for (int ps = 0; ps < SSTAGES - 1; ps++) SLOAD(ps, ps);

    for (int kt = 0; kt < NK; kt++) {
        CPA_WAITG(SSTAGES - 2);
        __syncthreads();
        uint32_t stg = sbase + (kt % SSTAGES) * SSTAGE_HALFS * 2;
        uint32_t As = stg;
        uint32_t Bs = stg + BM * HSTRIDE * 2;
        #pragma unroll
        for (int ks = 0; ks < 2; ks++) {
            const int k0 = ks * 16;
            uint32_t af[4][4], bf[4][2];
            #pragma unroll
            for (int i = 0; i < 4; i++) {
                uint32_t ad = As + ((wm*64 + i*16) * HSTRIDE + k0 + aoff) * 2;
                ldsm4(af[i][0], af[i][1], af[i][2], af[i][3], ad);
            }
            #pragma unroll
            for (int jp = 0; jp < 2; jp++) {
                uint32_t bd = Bs + ((wn*32 + jp*16) * HSTRIDE + k0 + boff) * 2;
                ldsm4(bf[jp*2][0], bf[jp*2][1], bf[jp*2+1][0], bf[jp*2+1][1], bd);
            }
            #pragma unroll
            for (int i = 0; i < 4; i++)
                #pragma unroll
                for (int j = 0; j < 4; j++)
                    hmma(acc[i][j], af[i], bf[j]);
        }
        int nxt = kt + SSTAGES - 1;
        if (nxt < NK) SLOAD(nxt % SSTAGES, nxt)
        else CPA_COMMIT();
    }

    #pragma unroll
    for (int i = 0; i < 4; i++) {
        #pragma unroll
        for (int j = 0; j < 4; j++) {
            int r0 = m0 + wm*64 + i*16 + (lane>>2);
            int c0 = n0 + wn*32 + j*8 + 2*(lane&3);
            long o0 = (long)r0 * ldo + c0;
            long o1 = o0 + (long)8 * ldo;
            float2 p0 = *(const float2*)(O + o0);
            float2 p1 = *(const float2*)(O + o1);
            *(float2*)(O + o0) = make_float2(acc[i][j][0] + p0.x, acc[i][j][1] + p0.y);
            *(float2*)(O + o1) = make_float2(acc[i][j][2] + p1.x, acc[i][j][3] + p1.y);
        }
    }
    #undef SLOAD
}

// ------------------------- RMSNorm -> fp16 output --------------------------
__global__ __launch_bounds__(256) void rmsnorm_h(
    const float* __restrict__ x, const float* __restrict__ w, __half* __restrict__ y)
{
    int row = blockIdx.x, tid = threadIdx.x;
    float4 v = ((const float4*)(x + (long)row * DMODEL))[tid];
    float ss = v.x*v.x + v.y*v.y + v.z*v.z + v.w*v.w;
    #pragma unroll
    for (int o = 16; o; o >>= 1) ss += __shfl_xor_sync(0xffffffffu, ss, o);
    __shared__ float sred[8];
    if ((tid & 31) == 0) sred[tid >> 5] = ss;
    __syncthreads();
    if (tid < 8) {
        float t = sred[tid];
        #pragma unroll
        for (int o = 4; o; o >>= 1) t += __shfl_xor_sync(0xffu, t, o);
        if (tid == 0) sred[0] = t;
    }
    __syncthreads();
    float scale = rsqrtf(sred[0] * (1.0f / DMODEL) + 1e-6f);
    float4 wv = ((const float4*)w)[tid];
    __half2 h01 = __floats2half2_rn(v.x*scale*wv.x, v.y*scale*wv.y);
    __half2 h23 = __floats2half2_rn(v.z*scale*wv.z, v.w*scale*wv.w);
    __half2* yp = (__half2*)(y + (long)row * DMODEL) + tid * 2;
    yp[0] = h01; yp[1] = h23;
}

// ------------------------- weight transpose -> fp16 ------------------------
__global__ void transpose_h(const float* __restrict__ W, __half* __restrict__ WT,
                            int K, int N)
{
    __shared__ float s[32][33];
    int n0 = blockIdx.x * 32, k0 = blockIdx.y * 32;
    int tx = threadIdx.x, ty = threadIdx.y;
    #pragma unroll
    for (int i = 0; i < 4; i++)
        s[ty + i * 8][tx] = W[(long)(k0 + ty + i * 8) * N + n0 + tx];
    __syncthreads();
    #pragma unroll
    for (int i = 0; i < 4; i++)
        WT[(long)(n0 + ty + i * 8) * K + k0 + tx] = __float2half_rn(s[tx][ty + i * 8]);
}

// ------------------------- scan over t (per (b,d) row) ---------------------
__global__ __launch_bounds__(256) void scan_kernel(
    const float* __restrict__ at, float* __restrict__ bt)
{
    long base = (long)blockIdx.x * SEQ;
    int tid = threadIdx.x;
    float la[16], lb[16];
    const float4* ap = (const float4*)(at + base) + tid * 4;
    float4*       bp = (float4*)(bt + base) + tid * 4;
    #pragma unroll
    for (int q = 0; q < 4; q++) { ((float4*)la)[q] = ap[q]; ((float4*)lb)[q] = bp[q]; }
    float A = 1.f, Bc = 0.f;
    #pragma unroll
    for (int j = 0; j < 16; j++) { Bc = la[j] * Bc + lb[j]; A *= la[j]; }
    __shared__ float sA[256], sB[256];
    sA[tid] = A; sB[tid] = Bc;
    __syncthreads();
    #pragma unroll
    for (int off = 1; off < 256; off <<= 1) {
        float pA = 1.f, pB = 0.f;
        if (tid >= off) { pA = sA[tid - off]; pB = sB[tid - off]; }
        float cA = sA[tid], cB = sB[tid];
        __syncthreads();
        sA[tid] = pA * cA;
        sB[tid] = cA * pB + cB;
        __syncthreads();
    }
    float carry = (tid > 0) ? sB[tid - 1] : 0.f;
    #pragma unroll
    for (int j = 0; j < 16; j++) { carry = la[j] * carry + lb[j]; lb[j] = carry; }
    #pragma unroll
    for (int q = 0; q < 4; q++) bp[q] = ((float4*)lb)[q];
}

// ------------------------- y[b,t,d] = x[b,t,d] + h[b,d,t] ------------------
__global__ void residual_add_t(
    const float* __restrict__ x, const float* __restrict__ ht, float* __restrict__ y)
{
    __shared__ float s[32][33];
    int t0 = blockIdx.x * 32, d0 = blockIdx.y * 32, bb = blockIdx.z;
    int tx = threadIdx.x, ty = threadIdx.y;
    #pragma unroll
    for (int i = 0; i < 4; i++)
        s[ty + i * 8][tx] = ht[((long)(bb * DMODEL + d0 + ty + i * 8)) * SEQ + t0 + tx];
    __syncthreads();
    #pragma unroll
    for (int i = 0; i < 4; i++) {
        long idx = ((long)(bb * SEQ + t0 + ty + i * 8)) * DMODEL + d0 + tx;
        y[idx] = x[idx] + s[tx][ty + i * 8];
    }
}

// ----------------------------------------------------------------------------
extern "C" void kernel_launch(void* const* d_in, const int* in_sizes, int n_in,
                              void* d_out, int out_size)
{
    const float* x   = (const float*)d_in[0];
    const float* Wg  = (const float*)d_in[1];
    const float* bg  = (const float*)d_in[2];
    const float* Wc  = (const float*)d_in[3];
    const float* bc  = (const float*)d_in[4];
    const float* n1w = (const float*)d_in[5];
    const float* n2w = (const float*)d_in[6];
    const float* W1  = (const float*)d_in[7];
    const float* W3  = (const float*)d_in[8];
    const float* W2  = (const float*)d_in[9];
    float* out = (float*)d_out;

    __half *hin, *fin, *u, *WgT, *WcT, *W1T, *W3T, *W2T;
    float *at, *bt;
    cudaGetSymbolAddress((void**)&hin, g_hin);
    cudaGetSymbolAddress((void**)&fin, g_fin);
    cudaGetSymbolAddress((void**)&at,  g_at);
    cudaGetSymbolAddress((void**)&bt,  g_bt);
    cudaGetSymbolAddress((void**)&u,   g_u);
    cudaGetSymbolAddress((void**)&WgT, g_WgT);
    cudaGetSymbolAddress((void**)&WcT, g_WcT);
    cudaGetSymbolAddress((void**)&W1T, g_W1T);
    cudaGetSymbolAddress((void**)&W3T, g_W3T);
    cudaGetSymbolAddress((void**)&W2T, g_W2T);

    cudaFuncSetAttribute(gemm_dual<M_GATES>, cudaFuncAttributeMaxDynamicSharedMemorySize, DSMEM);
    cudaFuncSetAttribute(gemm_dual<M_FF>,    cudaFuncAttributeMaxDynamicSharedMemorySize, DSMEM);
    cudaFuncSetAttribute(gemm_res,           cudaFuncAttributeMaxDynamicSharedMemorySize, SSMEM);

    // 0) weight transposes to [N,K] fp16
    transpose_h<<<dim3(DMODEL/32, DMODEL/32), dim3(32, 8)>>>(Wg, WgT, DMODEL, DMODEL);
    transpose_h<<<dim3(DMODEL/32, DMODEL/32), dim3(32, 8)>>>(Wc, WcT, DMODEL, DMODEL);
    transpose_h<<<dim3(DFF/32,    DMODEL/32), dim3(32, 8)>>>(W1, W1T, DMODEL, DFF);
    transpose_h<<<dim3(DFF/32,    DMODEL/32), dim3(32, 8)>>>(W3, W3T, DMODEL, DFF);
    transpose_h<<<dim3(DMODEL/32, DFF/32),    dim3(32, 8)>>>(W2, W2T, DFF, DMODEL);

    // 1) h_in = rmsnorm(x, n1_w) -> fp16
    rmsnorm_h<<<MTOK, 256>>>(x, n1w, hin);

    // 2) dual gates GEMM -> at = sigmoid(.), bt = (1-g)*tanh(.) in [b,d,t]
    gemm_dual<M_GATES><<<dim3(DMODEL/BN, MTOK/BM), 256, DSMEM>>>(
        hin, WgT, WcT, at, bt, nullptr, bg, bc, DMODEL);

    // 3) linear-recurrence scan along t (in place in bt)
    scan_kernel<<<BATCH * DMODEL, 256>>>(at, bt);

    // 4) x2 = x + h -> out
    residual_add_t<<<dim3(SEQ/32, DMODEL/32, BATCH), dim3(32, 8)>>>(x, bt, out);

    // 5) f_in = rmsnorm(x2, n2_w) -> fp16
    rmsnorm_h<<<MTOK, 256>>>(out, n2w, fin);

    // 6) dual FF GEMM -> u = half(silu(fin@W1T) * (fin@W3T))
    gemm_dual<M_FF><<<dim3(DFF/BN, MTOK/BM), 256, DSMEM>>>(
        fin, W1T, W3T, nullptr, nullptr, u, nullptr, nullptr, DMODEL);

    // 7) out = x2 + u@W2T (residual fused)
    gemm_res<<<dim3(DMODEL/BN, MTOK/BM), 256, SSMEM>>>(u, W2T, out, DFF, DMODEL);
}

// round 7
// speedup vs baseline: 7.9474x; 1.1168x over previous
#include <cuda_runtime.h>
#include <cuda_fp16.h>
#include <math.h>
#include <stdint.h>

#define BATCH 4
#define SEQ   4096
#define DMODEL 1024
#define DFF   4096
#define MTOK  (BATCH*SEQ)

// ---- dual-B kernel: 512 threads, BKK=64, 3 stages ----
#define BM 128
#define BN 128
#define DKK 64
#define HSTR_D 72                                    // 64 + 8 pad halfs
#define DSTAGES 3
#define DSTAGE_HALFS ((BM + 2*BN) * HSTR_D)          // 27648 halfs = 55296 B
#define DSMEM (DSTAGES * DSTAGE_HALFS * 2)           // 165888

// ---- single-B (W2): 256 threads, BKK=32, 4 stages, 2 CTAs/SM ----
#define SKK 32
#define HSTR_S 40
#define SSTAGES 4
#define SSTAGE_HALFS ((BM + BN) * HSTR_S)            // 10240 halfs = 20480 B
#define SSMEM (SSTAGES * SSTAGE_HALFS * 2)           // 81920

#define M_GATES 0
#define M_FF    1

// fused residual+norm kernel smem: 32 rows x 1033 floats
#define FR_STRIDE 1033
#define FRSMEM (32 * FR_STRIDE * 4)                  // 132224

// ------------------------- scratch -----------------------------------------
__device__ __half g_hin[MTOK*DMODEL];
__device__ __half g_fin[MTOK*DMODEL];
__device__ float  g_at [BATCH*DMODEL*SEQ];
__device__ float  g_bt [BATCH*DMODEL*SEQ];
__device__ __half g_u  [(size_t)MTOK*DFF];
__device__ __half g_WgT[DMODEL*DMODEL];
__device__ __half g_WcT[DMODEL*DMODEL];
__device__ __half g_W1T[(size_t)DFF*DMODEL];
__device__ __half g_W3T[(size_t)DFF*DMODEL];
__device__ __half g_W2T[(size_t)DMODEL*DFF];

// ------------------------- helpers -----------------------------------------
__device__ __forceinline__ uint32_t smem_u32(const void* p) {
    uint32_t a;
    asm("{ .reg .u64 t; cvta.to.shared.u64 t, %1; cvt.u32.u64 %0, t; }"
        : "=r"(a) : "l"(p));
    return a;
}
#define CPA16(dst, src) \
    asm volatile("cp.async.cg.shared.global [%0], [%1], 16;" :: "r"(dst), "l"(src))
#define CPA_COMMIT() asm volatile("cp.async.commit_group;" ::: "memory")
#define CPA_WAITG(n) asm volatile("cp.async.wait_group %0;" :: "n"(n) : "memory")

__device__ __forceinline__ void hmma(float c[4], const uint32_t a[4], const uint32_t b[2]) {
    asm volatile(
        "mma.sync.aligned.m16n8k16.row.col.f32.f16.f16.f32 "
        "{%0,%1,%2,%3},{%4,%5,%6,%7},{%8,%9},{%0,%1,%2,%3};"
        : "+f"(c[0]), "+f"(c[1]), "+f"(c[2]), "+f"(c[3])
        : "r"(a[0]), "r"(a[1]), "r"(a[2]), "r"(a[3]), "r"(b[0]), "r"(b[1]));
}
__device__ __forceinline__ void ldsm4(uint32_t& r0, uint32_t& r1, uint32_t& r2,
                                      uint32_t& r3, uint32_t addr) {
    asm volatile("ldmatrix.sync.aligned.m8n8.x4.shared.b16 {%0,%1,%2,%3}, [%4];"
                 : "=r"(r0), "=r"(r1), "=r"(r2), "=r"(r3) : "r"(addr));
}
__device__ __forceinline__ int a_lm_off(int lane, int stride) {
    return (lane & 15) * stride + 8 * (lane >> 4);
}
__device__ __forceinline__ int b_lm_off(int lane, int stride) {
    return ((lane & 7) + 8 * (lane >> 4)) * stride + 8 * ((lane >> 3) & 1);
}

// ------------------------- dual-B fp16 GEMM (512 thr) -----------------------
// acc1 = A@B1T^T, acc2 = A@B2T^T. Warp tile 32x32 per output, 4x4 warp grid.
template<int MODE>
__global__ __launch_bounds__(512, 1) void gemm_dual(
    const __half* __restrict__ A, const __half* __restrict__ B1T,
    const __half* __restrict__ B2T,
    float* __restrict__ O1, float* __restrict__ O2, __half* __restrict__ OU,
    const float* __restrict__ bias1, const float* __restrict__ bias2,
    int K)
{
    extern __shared__ __half smh[];
    const uint32_t sbase = smem_u32(smh);
    const int tid = threadIdx.x, lane = tid & 31, wid = tid >> 5;
    const int wm = wid & 3, wn = wid >> 2;     // 4x4 warps, 32x32 tile each
    const int m0 = blockIdx.y * BM, n0 = blockIdx.x * BN;
    const int NK = K / DKK;

    const int aoff = a_lm_off(lane, HSTR_D);
    const int boff = b_lm_off(lane, HSTR_D);

    float acc1[2][4][4] = {};
    float acc2[2][4][4] = {};

    #define DLOAD(stage, ktile)                                                   \
    {                                                                             \
        uint32_t base = sbase + (stage) * DSTAGE_HALFS * 2;                       \
        long koff = (long)(ktile) * DKK;                                          \
        _Pragma("unroll")                                                         \
        for (int i = 0; i < 6; i++) {                                             \
            int id = tid + i * 512;                                               \
            int row = id >> 3, ch = (id & 7) * 8;                                 \
            const __half* src;                                                    \
            if (row < 128)      src = A   + (long)(m0 + row)       * K + koff + ch; \
            else if (row < 256) src = B1T + (long)(n0 + row - 128) * K + koff + ch; \
            else                src = B2T + (long)(n0 + row - 256) * K + koff + ch; \
            CPA16(base + (row * HSTR_D + ch) * 2, src);                           \
        }                                                                         \
        CPA_COMMIT();                                                             \
    }

    #pragma unroll
    for (int ps = 0; ps < DSTAGES - 1; ps++) DLOAD(ps, ps);

    for (int kt = 0; kt < NK; kt++) {
        CPA_WAITG(DSTAGES - 2);
        __syncthreads();
        uint32_t stg = sbase + (kt % DSTAGES) * DSTAGE_HALFS * 2;
        uint32_t As  = stg;
        uint32_t B1s = stg + BM * HSTR_D * 2;
        uint32_t B2s = stg + (BM + BN) * HSTR_D * 2;
        #pragma unroll
        for (int ks = 0; ks < 4; ks++) {
            const int k0 = ks * 16;
            uint32_t af[2][4], bf1[4][2], bf2[4][2];
            #pragma unroll
            for (int i = 0; i < 2; i++) {
                uint32_t ad = As + ((wm*32 + i*16) * HSTR_D + k0 + aoff) * 2;
                ldsm4(af[i][0], af[i][1], af[i][2], af[i][3], ad);
            }
            #pragma unroll
            for (int jp = 0; jp < 2; jp++) {
                uint32_t bd1 = B1s + ((wn*32 + jp*16) * HSTR_D + k0 + boff) * 2;
                uint32_t bd2 = B2s + ((wn*32 + jp*16) * HSTR_D + k0 + boff) * 2;
                ldsm4(bf1[jp*2][0], bf1[jp*2][1], bf1[jp*2+1][0], bf1[jp*2+1][1], bd1);
                ldsm4(bf2[jp*2][0], bf2[jp*2][1], bf2[jp*2+1][0], bf2[jp*2+1][1], bd2);
            }
            #pragma unroll
            for (int i = 0; i < 2; i++)
                #pragma unroll
                for (int j = 0; j < 4; j++) {
                    hmma(acc1[i][j], af[i], bf1[j]);
                    hmma(acc2[i][j], af[i], bf2[j]);
                }
        }
        int nxt = kt + DSTAGES - 1;
        if (nxt < NK) DLOAD(nxt % DSTAGES, nxt)
        else CPA_COMMIT();
    }
    __syncthreads();   // smem reused for epilogue patches

    if (MODE == M_FF) {
        #pragma unroll
        for (int i = 0; i < 2; i++) {
            #pragma unroll
            for (int j = 0; j < 4; j++) {
                int r0 = m0 + wm*32 + i*16 + (lane>>2);
                int c0 = n0 + wn*32 + j*8 + 2*(lane&3);
                long o0 = (long)r0 * DFF + c0;
                long o1 = o0 + (long)8 * DFF;
                float a0 = acc1[i][j][0], a1 = acc1[i][j][1];
                float a2 = acc1[i][j][2], a3 = acc1[i][j][3];
                float v0 = a0 / (1.f + __expf(-a0)) * acc2[i][j][0];
                float v1 = a1 / (1.f + __expf(-a1)) * acc2[i][j][1];
                float v2 = a2 / (1.f + __expf(-a2)) * acc2[i][j][2];
                float v3 = a3 / (1.f + __expf(-a3)) * acc2[i][j][3];
                *(__half2*)(OU + o0) = __floats2half2_rn(v0, v1);
                *(__half2*)(OU + o1) = __floats2half2_rn(v2, v3);
            }
        }
    } else {
        float* patchG = (float*)smh + wid * 2 * (32 * 33);
        float* patchH = patchG + 32 * 33;
        #pragma unroll
        for (int i = 0; i < 2; i++) {
            #pragma unroll
            for (int j = 0; j < 4; j++) {
                int r0 = i*16 + (lane>>2);            // t-local 0..31
                int c0 = j*8 + 2*(lane&3);            // n-local 0..31
                int n  = n0 + wn*32 + c0;
                float b1a = bias1[n], b1b = bias1[n+1];
                float b2a = bias2[n], b2b = bias2[n+1];
                float g0 = 1.f / (1.f + __expf(-(acc1[i][j][0] + b1a)));
                float g1 = 1.f / (1.f + __expf(-(acc1[i][j][1] + b1b)));
                float g2 = 1.f / (1.f + __expf(-(acc1[i][j][2] + b1a)));
                float g3 = 1.f / (1.f + __expf(-(acc1[i][j][3] + b1b)));
                float h0 = (1.f - g0) * tanhf(acc2[i][j][0] + b2a);
                float h1 = (1.f - g1) * tanhf(acc2[i][j][1] + b2b);
                float h2 = (1.f - g2) * tanhf(acc2[i][j][2] + b2a);
                float h3 = (1.f - g3) * tanhf(acc2[i][j][3] + b2b);
                patchG[c0*33 + r0]       = g0;
                patchG[(c0+1)*33 + r0]   = g1;
                patchG[c0*33 + r0+8]     = g2;
                patchG[(c0+1)*33 + r0+8] = g3;
                patchH[c0*33 + r0]       = h0;
                patchH[(c0+1)*33 + r0]   = h1;
                patchH[c0*33 + r0+8]     = h2;
                patchH[(c0+1)*33 + r0+8] = h3;
            }
        }
        __syncwarp();
        int tokb = m0 + wm * 32;
        int b = tokb >> 12, tb = tokb & 4095;
        #pragma unroll 4
        for (int r = 0; r < 32; r++) {
            int n = n0 + wn*32 + r;
            long off = ((long)(b * DMODEL + n)) * SEQ + tb + lane;
            O1[off] = patchG[r*33 + lane];
            O2[off] = patchH[r*33 + lane];
        }
    }
    #undef DLOAD
}

// ------------------------- single-B fp16 GEMM: O += A@BT^T -----------------
__global__ __launch_bounds__(256, 2) void gemm_res(
    const __half* __restrict__ A, const __half* __restrict__ BT,
    float* __restrict__ O, int K, int ldo)
{
    extern __shared__ __half smh[];
    const uint32_t sbase = smem_u32(smh);
    const int tid = threadIdx.x, lane = tid & 31, wid = tid >> 5;
    const int wm = wid & 1, wn = wid >> 1;
    const int m0 = blockIdx.y * BM, n0 = blockIdx.x * BN;
    const int NK = K / SKK;

    const int aoff = a_lm_off(lane, HSTR_S);
    const int boff = b_lm_off(lane, HSTR_S);

    float acc[4][4][4] = {};

    #define SLOAD(stage, ktile)                                                   \
    {                                                                             \
        uint32_t base = sbase + (stage) * SSTAGE_HALFS * 2;                       \
        long koff = (long)(ktile) * SKK;                                          \
        _Pragma("unroll")                                                         \
        for (int i = 0; i < 4; i++) {                                             \
            int id = tid + i * 256;                                               \
            int row = id >> 2, ch = (id & 3) * 8;                                 \
            const __half* src;                                                    \
            if (row < 128) src = A  + (long)(m0 + row)       * K + koff + ch;     \
            else           src = BT + (long)(n0 + row - 128) * K + koff + ch;     \
            CPA16(base + (row * HSTR_S + ch) * 2, src);                           \
        }                                                                         \
        CPA_COMMIT();                                                             \
    }

    #pragma unroll
    for (int ps = 0; ps < SSTAGES - 1; ps++) SLOAD(ps, ps);

    for (int kt = 0; kt < NK; kt++) {
        CPA_WAITG(SSTAGES - 2);
        __syncthreads();
        uint32_t stg = sbase + (kt % SSTAGES) * SSTAGE_HALFS * 2;
        uint32_t As = stg;
        uint32_t Bs = stg + BM * HSTR_S * 2;
        #pragma unroll
        for (int ks = 0; ks < 2; ks++) {
            const int k0 = ks * 16;
            uint32_t af[4][4], bf[4][2];
            #pragma unroll
            for (int i = 0; i < 4; i++) {
                uint32_t ad = As + ((wm*64 + i*16) * HSTR_S + k0 + aoff) * 2;
                ldsm4(af[i][0], af[i][1], af[i][2], af[i][3], ad);
            }
            #pragma unroll
            for (int jp = 0; jp < 2; jp++) {
                uint32_t bd = Bs + ((wn*32 + jp*16) * HSTR_S + k0 + boff) * 2;
                ldsm4(bf[jp*2][0], bf[jp*2][1], bf[jp*2+1][0], bf[jp*2+1][1], bd);
            }
            #pragma unroll
            for (int i = 0; i < 4; i++)
                #pragma unroll
                for (int j = 0; j < 4; j++)
                    hmma(acc[i][j], af[i], bf[j]);
        }
        int nxt = kt + SSTAGES - 1;
        if (nxt < NK) SLOAD(nxt % SSTAGES, nxt)
        else CPA_COMMIT();
    }

    #pragma unroll
    for (int i = 0; i < 4; i++) {
        #pragma unroll
        for (int j = 0; j < 4; j++) {
            int r0 = m0 + wm*64 + i*16 + (lane>>2);
            int c0 = n0 + wn*32 + j*8 + 2*(lane&3);
            long o0 = (long)r0 * ldo + c0;
            long o1 = o0 + (long)8 * ldo;
            float2 p0 = *(const float2*)(O + o0);
            float2 p1 = *(const float2*)(O + o1);
            *(float2*)(O + o0) = make_float2(acc[i][j][0] + p0.x, acc[i][j][1] + p0.y);
            *(float2*)(O + o1) = make_float2(acc[i][j][2] + p1.x, acc[i][j][3] + p1.y);
        }
    }
    #undef SLOAD
}

// ------------------------- RMSNorm -> fp16 output --------------------------
__global__ __launch_bounds__(256) void rmsnorm_h(
    const float* __restrict__ x, const float* __restrict__ w, __half* __restrict__ y)
{
    int row = blockIdx.x, tid = threadIdx.x;
    float4 v = ((const float4*)(x + (long)row * DMODEL))[tid];
    float ss = v.x*v.x + v.y*v.y + v.z*v.z + v.w*v.w;
    #pragma unroll
    for (int o = 16; o; o >>= 1) ss += __shfl_xor_sync(0xffffffffu, ss, o);
    __shared__ float sred[8];
    if ((tid & 31) == 0) sred[tid >> 5] = ss;
    __syncthreads();
    if (tid < 8) {
        float t = sred[tid];
        #pragma unroll
        for (int o = 4; o; o >>= 1) t += __shfl_xor_sync(0xffu, t, o);
        if (tid == 0) sred[0] = t;
    }
    __syncthreads();
    float scale = rsqrtf(sred[0] * (1.0f / DMODEL) + 1e-6f);
    float4 wv = ((const float4*)w)[tid];
    __half2 h01 = __floats2half2_rn(v.x*scale*wv.x, v.y*scale*wv.y);
    __half2 h23 = __floats2half2_rn(v.z*scale*wv.z, v.w*scale*wv.w);
    __half2* yp = (__half2*)(y + (long)row * DMODEL) + tid * 2;
    yp[0] = h01; yp[1] = h23;
}

// ---------- fused: x2 = x + h^T; out=x2 (f32); fin = rmsnorm(x2)*w (fp16) ---
// grid (SEQ/32, BATCH), 256 threads. smem slab 32 tokens x 1024 d.
__global__ __launch_bounds__(256) void fuse_res_norm(
    const float* __restrict__ x, const float* __restrict__ ht,
    const float* __restrict__ w,
    float* __restrict__ out, __half* __restrict__ fin)
{
    extern __shared__ float slab[];            // [32][FR_STRIDE]
    const int t0 = blockIdx.x * 32, b = blockIdx.y;
    const int tid = threadIdx.x, lane = tid & 31, wid = tid >> 5;

    // stage h[b, :, t0:t0+32] transposed into slab[t][d]
    for (int dc = 0; dc < 32; dc++) {
        int d = dc * 8 + wid;                   // 8 d-rows per pass
        const float* src = ht + ((long)(b * DMODEL + d)) * SEQ + t0;
        float v = src[lane];
        slab[lane * FR_STRIDE + d] = v;
        d += 256;  // cover 1024 d in 4 sub-passes? no — handled by dc loop
        (void)d;
    }
    // The loop above covers d = dc*8 + wid for dc in 0..31 -> d in 0..255 only
    // for wid<8. Extend: three more groups.
    for (int g = 1; g < 4; g++) {
        for (int dc = 0; dc < 32; dc++) {
            int d = g * 256 + dc * 8 + wid;
            const float* src = ht + ((long)(b * DMODEL + d)) * SEQ + t0;
            slab[lane * FR_STRIDE + d] = src[lane];
        }
    }
    __syncthreads();

    // each warp handles 4 tokens
    #pragma unroll
    for (int k = 0; k < 4; k++) {
        int tt = wid * 4 + k;
        int tok = b * SEQ + t0 + tt;
        float* row = slab + tt * FR_STRIDE;
        const float* xr = x + (long)tok * DMODEL;
        float ss = 0.f;
        float vals[32];
        #pragma unroll
        for (int q = 0; q < 32; q++) {
            float v = xr[q * 32 + lane] + row[q * 32 + lane];
            vals[q] = v;
            ss += v * v;
        }
        #pragma unroll
        for (int o = 16; o; o >>= 1) ss += __shfl_xor_sync(0xffffffffu, ss, o);
        float scale = rsqrtf(ss * (1.0f / DMODEL) + 1e-6f);
        float* orow = out + (long)tok * DMODEL;
        __half* frow = fin + (long)tok * DMODEL;
        #pragma unroll
        for (int q = 0; q < 32; q++) {
            int d = q * 32 + lane;
            orow[d] = vals[q];
            frow[d] = __float2half_rn(vals[q] * scale * w[d]);
        }
    }
}

// ------------------------- weight transpose -> fp16 ------------------------
__global__ void transpose_h(const float* __restrict__ W, __half* __restrict__ WT,
                            int K, int N)
{
    __shared__ float s[32][33];
    int n0 = blockIdx.x * 32, k0 = blockIdx.y * 32;
    int tx = threadIdx.x, ty = threadIdx.y;
    #pragma unroll
    for (int i = 0; i < 4; i++)
        s[ty + i * 8][tx] = W[(long)(k0 + ty + i * 8) * N + n0 + tx];
    __syncthreads();
    #pragma unroll
    for (int i = 0; i < 4; i++)
        WT[(long)(n0 + ty + i * 8) * K + k0 + tx] = __float2half_rn(s[tx][ty + i * 8]);
}

// ------------------------- scan over t (per (b,d) row) ---------------------
__global__ __launch_bounds__(256) void scan_kernel(
    const float* __restrict__ at, float* __restrict__ bt)
{
    long base = (long)blockIdx.x * SEQ;
    int tid = threadIdx.x;
    float la[16], lb[16];
    const float4* ap = (const float4*)(at + base) + tid * 4;
    float4*       bp = (float4*)(bt + base) + tid * 4;
    #pragma unroll
    for (int q = 0; q < 4; q++) { ((float4*)la)[q] = ap[q]; ((float4*)lb)[q] = bp[q]; }
    float A = 1.f, Bc = 0.f;
    #pragma unroll
    for (int j = 0; j < 16; j++) { Bc = la[j] * Bc + lb[j]; A *= la[j]; }
    __shared__ float sA[256], sB[256];
    sA[tid] = A; sB[tid] = Bc;
    __syncthreads();
    #pragma unroll
    for (int off = 1; off < 256; off <<= 1) {
        float pA = 1.f, pB = 0.f;
        if (tid >= off) { pA = sA[tid - off]; pB = sB[tid - off]; }
        float cA = sA[tid], cB = sB[tid];
        __syncthreads();
        sA[tid] = pA * cA;
        sB[tid] = cA * pB + cB;
        __syncthreads();
    }
    float carry = (tid > 0) ? sB[tid - 1] : 0.f;
    #pragma unroll
    for (int j = 0; j < 16; j++) { carry = la[j] * carry + lb[j]; lb[j] = carry; }
    #pragma unroll
    for (int q = 0; q < 4; q++) bp[q] = ((float4*)lb)[q];
}

// ----------------------------------------------------------------------------
extern "C" void kernel_launch(void* const* d_in, const int* in_sizes, int n_in,
                              void* d_out, int out_size)
{
    const float* x   = (const float*)d_in[0];
    const float* Wg  = (const float*)d_in[1];
    const float* bg  = (const float*)d_in[2];
    const float* Wc  = (const float*)d_in[3];
    const float* bc  = (const float*)d_in[4];
    const float* n1w = (const float*)d_in[5];
    const float* n2w = (const float*)d_in[6];
    const float* W1  = (const float*)d_in[7];
    const float* W3  = (const float*)d_in[8];
    const float* W2  = (const float*)d_in[9];
    float* out = (float*)d_out;

    __half *hin, *fin, *u, *WgT, *WcT, *W1T, *W3T, *W2T;
    float *at, *bt;
    cudaGetSymbolAddress((void**)&hin, g_hin);
    cudaGetSymbolAddress((void**)&fin, g_fin);
    cudaGetSymbolAddress((void**)&at,  g_at);
    cudaGetSymbolAddress((void**)&bt,  g_bt);
    cudaGetSymbolAddress((void**)&u,   g_u);
    cudaGetSymbolAddress((void**)&WgT, g_WgT);
    cudaGetSymbolAddress((void**)&WcT, g_WcT);
    cudaGetSymbolAddress((void**)&W1T, g_W1T);
    cudaGetSymbolAddress((void**)&W3T, g_W3T);
    cudaGetSymbolAddress((void**)&W2T, g_W2T);

    cudaFuncSetAttribute(gemm_dual<M_GATES>, cudaFuncAttributeMaxDynamicSharedMemorySize, DSMEM);
    cudaFuncSetAttribute(gemm_dual<M_FF>,    cudaFuncAttributeMaxDynamicSharedMemorySize, DSMEM);
    cudaFuncSetAttribute(gemm_res,           cudaFuncAttributeMaxDynamicSharedMemorySize, SSMEM);
    cudaFuncSetAttribute(fuse_res_norm,      cudaFuncAttributeMaxDynamicSharedMemorySize, FRSMEM);

    // 0) weight transposes to [N,K] fp16
    transpose_h<<<dim3(DMODEL/32, DMODEL/32), dim3(32, 8)>>>(Wg, WgT, DMODEL, DMODEL);
    transpose_h<<<dim3(DMODEL/32, DMODEL/32), dim3(32, 8)>>>(Wc, WcT, DMODEL, DMODEL);
    transpose_h<<<dim3(DFF/32,    DMODEL/32), dim3(32, 8)>>>(W1, W1T, DMODEL, DFF);
    transpose_h<<<dim3(DFF/32,    DMODEL/32), dim3(32, 8)>>>(W3, W3T, DMODEL, DFF);
    transpose_h<<<dim3(DMODEL/32, DFF/32),    dim3(32, 8)>>>(W2, W2T, DFF, DMODEL);

    // 1) h_in = rmsnorm(x, n1_w) -> fp16
    rmsnorm_h<<<MTOK, 256>>>(x, n1w, hin);

    // 2) dual gates GEMM -> at = sigmoid(.), bt = (1-g)*tanh(.) in [b,d,t]
    gemm_dual<M_GATES><<<dim3(DMODEL/BN, MTOK/BM), 512, DSMEM>>>(
        hin, WgT, WcT, at, bt, nullptr, bg, bc, DMODEL);

    // 3) linear-recurrence scan along t (in place in bt)
    scan_kernel<<<BATCH * DMODEL, 256>>>(at, bt);

    // 4+5) out = x + h; fin = rmsnorm(out, n2_w) (fused)
    fuse_res_norm<<<dim3(SEQ/32, BATCH), 256, FRSMEM>>>(x, bt, n2w, out, fin);

    // 6) dual FF GEMM -> u = half(silu(fin@W1T) * (fin@W3T))
    gemm_dual<M_FF><<<dim3(DFF/BN, MTOK/BM), 512, DSMEM>>>(
        fin, W1T, W3T, nullptr, nullptr, u, nullptr, nullptr, DMODEL);

    // 7) out = x2 + u@W2T (residual fused)
    gemm_res<<<dim3(DMODEL/BN, MTOK/BM), 256, SSMEM>>>(u, W2T, out, DFF, DMODEL);
}